// round 8
// baseline (speedup 1.0000x reference)
#include <cuda_runtime.h>
#include <math.h>
#include <stdint.h>

// Problem constants
#define TT   2048
#define HH   2048
#define NHD  16
#define HD   128
#define NE   16
#define TOPK 2
#define FF   1024
#define FSH  4096
#define EPSV 1e-6f

// ---------------------------------------------------------------------------
// Scratch (device globals; allocation-free per harness rules)
// ---------------------------------------------------------------------------
__device__ float g_h1[TT * HH];
__device__ float g_qkv[TT * 3 * HH];
__device__ float g_ctx[TT * HH];
__device__ float g_x1[TT * HH];
__device__ float g_h2[TT * HH];
__device__ float g_gu[TT * TOPK * 2 * FF];   // reused as eout after act
__device__ float g_act[TT * TOPK * FF];
__device__ float g_sg[TT * 2 * FSH];
__device__ float g_sact[TT * FSH];
__device__ int   g_topi[TT * TOPK];
__device__ float g_topw[TT * TOPK];
__device__ int   g_cnt[NE];
__device__ int   g_off[NE];
__device__ int   g_cur[NE];
__device__ int   g_stok[TT * TOPK];
__device__ int   g_sof[TT * TOPK];

// ---------------------------------------------------------------------------
// TF32 helpers
// ---------------------------------------------------------------------------
__device__ __forceinline__ float to_tf32(float x) {
    uint32_t u;
    asm("cvt.rna.tf32.f32 %0, %1;" : "=r"(u) : "f"(x));
    return __uint_as_float(u);
}

// split x into (hi, lo) tf32 pair; x ≈ hi + lo to ~2^-22 relative
__device__ __forceinline__ float2 split2(float x) {
    float h = to_tf32(x);
    float l = to_tf32(x - h);
    return make_float2(h, l);
}

__device__ __forceinline__ void tf32_split(float x, uint32_t& hi, uint32_t& lo) {
    float h = to_tf32(x);
    float l = to_tf32(x - h);
    hi = __float_as_uint(h);
    lo = __float_as_uint(l);
}

__device__ __forceinline__ void mma_tf32(float& c0, float& c1, float& c2, float& c3,
                                         uint32_t a0, uint32_t a1, uint32_t a2, uint32_t a3,
                                         uint32_t b0, uint32_t b1) {
    asm volatile(
        "mma.sync.aligned.m16n8k8.row.col.f32.tf32.tf32.f32 "
        "{%0,%1,%2,%3}, {%4,%5,%6,%7}, {%8,%9}, {%0,%1,%2,%3};"
        : "+f"(c0), "+f"(c1), "+f"(c2), "+f"(c3)
        : "r"(a0), "r"(a1), "r"(a2), "r"(a3), "r"(b0), "r"(b1));
}

// ---------------------------------------------------------------------------
// RMSNorm: one block per row
// ---------------------------------------------------------------------------
__global__ void rmsnorm_kernel(const float* __restrict__ x, const float* __restrict__ g,
                               float* __restrict__ o) {
    int t = blockIdx.x;
    const float4* xr = (const float4*)(x + (size_t)t * HH);
    const float4* gr = (const float4*)g;
    float4* orow = (float4*)(o + (size_t)t * HH);
    float4 v[2];
    float ss = 0.f;
#pragma unroll
    for (int it = 0; it < 2; it++) {
        v[it] = xr[threadIdx.x + it * 256];
        ss += v[it].x * v[it].x + v[it].y * v[it].y + v[it].z * v[it].z + v[it].w * v[it].w;
    }
#pragma unroll
    for (int d = 16; d; d >>= 1) ss += __shfl_xor_sync(0xffffffffu, ss, d);
    __shared__ float red[8];
    __shared__ float sscale;
    int w = threadIdx.x >> 5, l = threadIdx.x & 31;
    if (l == 0) red[w] = ss;
    __syncthreads();
    if (threadIdx.x == 0) {
        float s2 = 0.f;
#pragma unroll
        for (int i = 0; i < 8; i++) s2 += red[i];
        sscale = rsqrtf(s2 / (float)HH + EPSV);
    }
    __syncthreads();
    float sc = sscale;
#pragma unroll
    for (int it = 0; it < 2; it++) {
        float4 gv = gr[threadIdx.x + it * 256];
        float4 r;
        r.x = v[it].x * sc * gv.x;
        r.y = v[it].y * sc * gv.y;
        r.z = v[it].z * sc * gv.z;
        r.w = v[it].w * sc * gv.w;
        orow[threadIdx.x + it * 256] = r;
    }
}

// ---------------------------------------------------------------------------
// 3xTF32 tensor-core GEMM (fp32-accurate), 128x128 CTA tile, K-tile 16,
// 256 threads (8 warps), warp layout 2(m) x 4(n), each warp 64x32 via
// 4x4 m16n8k8 tiles. smem holds PRE-SPLIT tf32 (hi,lo) float2 per element
// (split once at store; inner loop is pure LDS.64 + HMMA). Row stride 132
// float2 = 264 words (≡8 mod 32): conflict-free 64-bit fragment loads.
// acc += Ahi*Blo + Alo*Bhi + Ahi*Bhi. Register prefetch + double-buffered.
// MODE 0: C = A@B      MODE 1: C = A@B + D
// MODE 2: MoE up (A rows gathered via slot_tok, per-expert B, C by slot)
// MODE 3: MoE down (A/C rows contiguous per-expert slots, per-expert B)
// ---------------------------------------------------------------------------
#define KT 16
#define SST2 132   // smem row stride (float2 elements)
#define GEMM_SMEM_BYTES (4 * KT * SST2 * 8)   // As[2 bufs] + Bs[2 bufs]

template <int MODE>
__global__ void __launch_bounds__(256, 2)
sgemm_k(const float* __restrict__ A, const float* __restrict__ B, float* __restrict__ C,
        const float* __restrict__ D, int M, int N, int Kd,
        const int* __restrict__ slot_tok, const int* __restrict__ off,
        const int* __restrict__ cnt) {
    extern __shared__ float2 dsm[];
    float2* As = dsm;                       // [2][KT][SST2]
    float2* Bs = dsm + 2 * KT * SST2;       // [2][KT][SST2]

    const int tid = threadIdx.x;
    int Me = M, base = 0;
    const float* Bp = B;
    if (MODE >= 2) {
        int e = blockIdx.z;
        Me = cnt[e];
        base = off[e];
        Bp = B + (size_t)e * Kd * N;
    }
    int m0 = blockIdx.y * 128;
    if (m0 >= Me) return;
    int n0 = blockIdx.x * 128;

    // ---- global load mapping ----
    int aRow = tid >> 1;
    int aSel = tid & 1;           // which 8-k half
    bool aValid = (m0 + aRow) < Me;
    size_t aIdx = 0;
    if (MODE == 2) {
        aIdx = aValid ? (size_t)slot_tok[base + m0 + aRow] * Kd : 0;
    } else if (MODE == 3) {
        aIdx = (size_t)(base + m0 + aRow) * Kd;
    } else {
        aIdx = (size_t)(m0 + aRow) * Kd;
    }
    int bRow = tid >> 4;
    int bC4 = (tid & 15) << 2;
    const float* bPtr = Bp + (size_t)bRow * N + n0 + bC4;

    // ---- mma thread mapping ----
    const int lane = tid & 31;
    const int g = lane >> 2;       // group id 0..7
    const int tig = lane & 3;      // thread in group 0..3
    const int wid = tid >> 5;
    const int warp_m = wid >> 2;   // 0..1
    const int warp_n = wid & 3;    // 0..3

    float acc[4][4][4];
#pragma unroll
    for (int i = 0; i < 4; i++)
#pragma unroll
        for (int j = 0; j < 4; j++)
#pragma unroll
            for (int c = 0; c < 4; c++) acc[i][j][c] = 0.f;

    // ---- prologue: tile 0, split to (hi,lo) at store ----
    float4 av0 = make_float4(0.f, 0.f, 0.f, 0.f), av1 = av0;
    if (aValid) {
        av0 = *(const float4*)(A + aIdx + aSel * 8);
        av1 = *(const float4*)(A + aIdx + aSel * 8 + 4);
    }
    float4 bv0 = *(const float4*)bPtr;
    float4 bv1 = *(const float4*)(bPtr + 64);
    {
        int ak = aSel * 8;
        As[(ak + 0) * SST2 + aRow] = split2(av0.x);
        As[(ak + 1) * SST2 + aRow] = split2(av0.y);
        As[(ak + 2) * SST2 + aRow] = split2(av0.z);
        As[(ak + 3) * SST2 + aRow] = split2(av0.w);
        As[(ak + 4) * SST2 + aRow] = split2(av1.x);
        As[(ak + 5) * SST2 + aRow] = split2(av1.y);
        As[(ak + 6) * SST2 + aRow] = split2(av1.z);
        As[(ak + 7) * SST2 + aRow] = split2(av1.w);
        float2* brow = &Bs[bRow * SST2];
        brow[bC4 + 0] = split2(bv0.x);
        brow[bC4 + 1] = split2(bv0.y);
        brow[bC4 + 2] = split2(bv0.z);
        brow[bC4 + 3] = split2(bv0.w);
        brow[bC4 + 64] = split2(bv1.x);
        brow[bC4 + 65] = split2(bv1.y);
        brow[bC4 + 66] = split2(bv1.z);
        brow[bC4 + 67] = split2(bv1.w);
    }
    __syncthreads();

    int buf = 0;
    for (int k0 = 0; k0 < Kd; k0 += KT) {
        int kn = k0 + KT;
        bool more = kn < Kd;
        if (more) {
            if (aValid) {
                av0 = *(const float4*)(A + aIdx + kn + aSel * 8);
                av1 = *(const float4*)(A + aIdx + kn + aSel * 8 + 4);
            }
            bv0 = *(const float4*)(bPtr + (size_t)kn * N);
            bv1 = *(const float4*)(bPtr + (size_t)kn * N + 64);
        }

        // ---- compute 2 k8 steps from pre-split smem ----
#pragma unroll
        for (int kk8 = 0; kk8 < KT; kk8 += 8) {
            const float2* Ab0 = &As[(buf * KT + kk8 + tig) * SST2];
            const float2* Ab4 = &As[(buf * KT + kk8 + tig + 4) * SST2];
            const float2* Bb0 = &Bs[(buf * KT + kk8 + tig) * SST2 + warp_n * 32];
            const float2* Bb4 = &Bs[(buf * KT + kk8 + tig + 4) * SST2 + warp_n * 32];
            float2 b0[4], b1[4];
#pragma unroll
            for (int j = 0; j < 4; j++) {
                b0[j] = Bb0[j * 8 + g];
                b1[j] = Bb4[j * 8 + g];
            }
#pragma unroll
            for (int i = 0; i < 4; i++) {
                int m = warp_m * 64 + i * 16 + g;
                float2 a0 = Ab0[m];
                float2 a1 = Ab0[m + 8];
                float2 a2 = Ab4[m];
                float2 a3 = Ab4[m + 8];
                uint32_t ah0 = __float_as_uint(a0.x), al0 = __float_as_uint(a0.y);
                uint32_t ah1 = __float_as_uint(a1.x), al1 = __float_as_uint(a1.y);
                uint32_t ah2 = __float_as_uint(a2.x), al2 = __float_as_uint(a2.y);
                uint32_t ah3 = __float_as_uint(a3.x), al3 = __float_as_uint(a3.y);
#pragma unroll
                for (int j = 0; j < 4; j++) {
                    uint32_t bh0 = __float_as_uint(b0[j].x), bl0 = __float_as_uint(b0[j].y);
                    uint32_t bh1 = __float_as_uint(b1[j].x), bl1 = __float_as_uint(b1[j].y);
                    mma_tf32(acc[i][j][0], acc[i][j][1], acc[i][j][2], acc[i][j][3],
                             ah0, ah1, ah2, ah3, bl0, bl1);
                    mma_tf32(acc[i][j][0], acc[i][j][1], acc[i][j][2], acc[i][j][3],
                             al0, al1, al2, al3, bh0, bh1);
                    mma_tf32(acc[i][j][0], acc[i][j][1], acc[i][j][2], acc[i][j][3],
                             ah0, ah1, ah2, ah3, bh0, bh1);
                }
            }
        }

        if (more) {
            int nb = buf ^ 1;
            int ak = aSel * 8;
            float2* Asn = &As[nb * KT * SST2];
            Asn[(ak + 0) * SST2 + aRow] = split2(av0.x);
            Asn[(ak + 1) * SST2 + aRow] = split2(av0.y);
            Asn[(ak + 2) * SST2 + aRow] = split2(av0.z);
            Asn[(ak + 3) * SST2 + aRow] = split2(av0.w);
            Asn[(ak + 4) * SST2 + aRow] = split2(av1.x);
            Asn[(ak + 5) * SST2 + aRow] = split2(av1.y);
            Asn[(ak + 6) * SST2 + aRow] = split2(av1.z);
            Asn[(ak + 7) * SST2 + aRow] = split2(av1.w);
            float2* brow = &Bs[(nb * KT + bRow) * SST2];
            brow[bC4 + 0] = split2(bv0.x);
            brow[bC4 + 1] = split2(bv0.y);
            brow[bC4 + 2] = split2(bv0.z);
            brow[bC4 + 3] = split2(bv0.w);
            brow[bC4 + 64] = split2(bv1.x);
            brow[bC4 + 65] = split2(bv1.y);
            brow[bC4 + 66] = split2(bv1.z);
            brow[bC4 + 67] = split2(bv1.w);
            __syncthreads();
            buf = nb;
        }
    }

    // ---- epilogue ----
#pragma unroll
    for (int i = 0; i < 4; i++) {
        int r0i = m0 + warp_m * 64 + i * 16 + g;
        int r1i = r0i + 8;
#pragma unroll
        for (int j = 0; j < 4; j++) {
            int col = n0 + warp_n * 32 + j * 8 + 2 * tig;
            if (MODE < 2 || r0i < Me) {
                size_t crow = (MODE >= 2) ? (size_t)(base + r0i) : (size_t)r0i;
                float2 cv = make_float2(acc[i][j][0], acc[i][j][1]);
                if (MODE == 1) {
                    float2 dv = *(const float2*)(D + (size_t)r0i * N + col);
                    cv.x += dv.x; cv.y += dv.y;
                }
                *(float2*)(C + crow * N + col) = cv;
            }
            if (MODE < 2 || r1i < Me) {
                size_t crow = (MODE >= 2) ? (size_t)(base + r1i) : (size_t)r1i;
                float2 cv = make_float2(acc[i][j][2], acc[i][j][3]);
                if (MODE == 1) {
                    float2 dv = *(const float2*)(D + (size_t)r1i * N + col);
                    cv.x += dv.x; cv.y += dv.y;
                }
                *(float2*)(C + crow * N + col) = cv;
            }
        }
    }
}

// ---------------------------------------------------------------------------
// RoPE in-place on q,k inside g_qkv
// ---------------------------------------------------------------------------
__global__ void rope_kernel(float* __restrict__ qkv) {
    int t = blockIdx.x;
    for (int idx = threadIdx.x; idx < NHD * 64; idx += blockDim.x) {
        int h = idx >> 6, i = idx & 63;
        // 10000^(-i/64) = exp2(-i/64 * log2(10000))
        float inv = exp2f(-(float)i * (13.287712379549449f / 64.f));
        float ang = (float)t * inv;
        float c = cosf(ang), s = sinf(ang);
        float* q = qkv + (size_t)t * 6144 + h * HD;
        float* k = q + 2048;
        float q1 = q[i], q2 = q[i + 64];
        q[i] = q1 * c - q2 * s;
        q[i + 64] = q1 * s + q2 * c;
        float k1 = k[i], k2 = k[i + 64];
        k[i] = k1 * c - k2 * s;
        k[i + 64] = k1 * s + k2 * c;
    }
}

// ---------------------------------------------------------------------------
// Flash attention: QK^T via 3xTF32 tensor cores, softmax + PV in fp32 SIMT.
// Block = (64 queries, one head); iterates 64-key tiles. Heavy q-blocks
// scheduled first (qb reversed) for LPT-style balance of triangular work.
// ---------------------------------------------------------------------------
#define QS 132
#define KS 132
#define VSD 132
#define SPS 68
#define ATTN_SMEM_FLOATS (64 * QS + 64 * KS + 64 * VSD + 64 * SPS + 64 * 16 + 3 * 64)

__global__ void __launch_bounds__(256, 1)
attn_kernel(const float* __restrict__ qkv, float* __restrict__ ctx) {
    extern __shared__ float sm[];
    float* sQ = sm;                  // 64 x QS   (q row-major)
    float* sK = sQ + 64 * QS;        // 64 x KS   (k row-major)
    float* sV = sK + 64 * KS;        // 64 x VSD
    float* sP = sV + 64 * VSD;       // 64 x SPS  (scores / probs)
    float* sRed = sP + 64 * SPS;     // 64 x 16
    float* sM = sRed + 64 * 16;
    float* sL = sM + 64;
    float* sF = sL + 64;

    const int tid = threadIdx.x;
    const int qb = (int)gridDim.x - 1 - (int)blockIdx.x;  // heavy blocks first
    const int h = blockIdx.y;
    const int ty = tid >> 4, tx = tid & 15;
    const int lane = tid & 31, g = lane >> 2, tig = lane & 3;
    const int wid = tid >> 5;
    const int wqm = wid >> 1;        // 0..3: QK warp m16-row block
    const int wqn = wid & 1;         // 0..1: QK warp n32-col block
    const float iss = 0.08838834764831845f;  // 1/sqrt(128)

#pragma unroll
    for (int it = 0; it < 8; it++) {
        int idx = it * 256 + tid;
        int r = idx >> 5, c4 = (idx & 31) << 2;
        float4 qv = *(const float4*)(qkv + (size_t)(qb * 64 + r) * 6144 + h * HD + c4);
        *(float4*)&sQ[r * QS + c4] = qv;
    }
    if (tid < 64) { sM[tid] = -1e30f; sL[tid] = 0.f; }

    float oacc[4][8];
#pragma unroll
    for (int i = 0; i < 4; i++)
#pragma unroll
        for (int j = 0; j < 8; j++) oacc[i][j] = 0.f;

    for (int kb = 0; kb <= qb; kb++) {
        __syncthreads();
#pragma unroll
        for (int it = 0; it < 8; it++) {
            int idx = it * 256 + tid;
            int r = idx >> 5, c4 = (idx & 31) << 2;
            const float* bp = qkv + (size_t)(kb * 64 + r) * 6144 + 2048 + h * HD + c4;
            float4 kv = *(const float4*)bp;
            *(float4*)&sK[r * KS + c4] = kv;
            float4 vv = *(const float4*)(bp + 2048);
            *(float4*)&sV[r * VSD + c4] = vv;
        }
        __syncthreads();

        // ---- S = Q @ K^T via 3xTF32 mma; each warp computes 16x32 ----
        float qacc[4][4];
#pragma unroll
        for (int j = 0; j < 4; j++)
#pragma unroll
            for (int c = 0; c < 4; c++) qacc[j][c] = 0.f;

#pragma unroll 4
        for (int d8 = 0; d8 < HD; d8 += 8) {
            uint32_t ah0, al0, ah1, al1, ah2, al2, ah3, al3;
            tf32_split(sQ[(wqm * 16 + g) * QS + d8 + tig],     ah0, al0);
            tf32_split(sQ[(wqm * 16 + g + 8) * QS + d8 + tig], ah1, al1);
            tf32_split(sQ[(wqm * 16 + g) * QS + d8 + tig + 4],     ah2, al2);
            tf32_split(sQ[(wqm * 16 + g + 8) * QS + d8 + tig + 4], ah3, al3);
#pragma unroll
            for (int j = 0; j < 4; j++) {
                uint32_t bh0, bl0, bh1, bl1;
                int krow = wqn * 32 + j * 8 + g;
                tf32_split(sK[krow * KS + d8 + tig],     bh0, bl0);
                tf32_split(sK[krow * KS + d8 + tig + 4], bh1, bl1);
                mma_tf32(qacc[j][0], qacc[j][1], qacc[j][2], qacc[j][3],
                         ah0, ah1, ah2, ah3, bl0, bl1);
                mma_tf32(qacc[j][0], qacc[j][1], qacc[j][2], qacc[j][3],
                         al0, al1, al2, al3, bh0, bh1);
                mma_tf32(qacc[j][0], qacc[j][1], qacc[j][2], qacc[j][3],
                         ah0, ah1, ah2, ah3, bh0, bh1);
            }
        }

        // write raw S to sP (mma C layout: rows g/g+8, cols 2tig/2tig+1)
#pragma unroll
        for (int j = 0; j < 4; j++) {
            int col = wqn * 32 + j * 8 + 2 * tig;
            *(float2*)&sP[(wqm * 16 + g) * SPS + col] =
                make_float2(qacc[j][0], qacc[j][1]);
            *(float2*)&sP[(wqm * 16 + g + 8) * SPS + col] =
                make_float2(qacc[j][2], qacc[j][3]);
        }
        __syncthreads();

        // ---- read 4x4 ownership block; scale + causal mask ----
        float sacc[4][4];
#pragma unroll
        for (int i = 0; i < 4; i++)
#pragma unroll
            for (int j = 0; j < 4; j++)
                sacc[i][j] = sP[(ty * 4 + i) * SPS + tx * 4 + j];

        if (kb == qb) {
#pragma unroll
            for (int i = 0; i < 4; i++) {
                int qi = ty * 4 + i;
#pragma unroll
                for (int j = 0; j < 4; j++) {
                    int kj = tx * 4 + j;
                    float s = sacc[i][j] * iss;
                    sacc[i][j] = (kj > qi) ? -1e30f : s;
                }
            }
        } else {
#pragma unroll
            for (int i = 0; i < 4; i++)
#pragma unroll
                for (int j = 0; j < 4; j++) sacc[i][j] *= iss;
        }

        // row max
#pragma unroll
        for (int i = 0; i < 4; i++) {
            float lm = fmaxf(fmaxf(sacc[i][0], sacc[i][1]), fmaxf(sacc[i][2], sacc[i][3]));
            sRed[(ty * 4 + i) * 16 + tx] = lm;
        }
        __syncthreads();
        if (tid < 64) {
            float m_old = sM[tid];
            float tm = -1e30f;
#pragma unroll
            for (int c = 0; c < 16; c++) tm = fmaxf(tm, sRed[tid * 16 + c]);
            float m_new = fmaxf(m_old, tm);
            sM[tid] = m_new;
            sF[tid] = expf(m_old - m_new);
        }
        __syncthreads();

        // P = exp(S - m), row sums
#pragma unroll
        for (int i = 0; i < 4; i++) {
            int row = ty * 4 + i;
            float m = sM[row];
            float rs = 0.f;
#pragma unroll
            for (int j = 0; j < 4; j++) {
                float p = expf(sacc[i][j] - m);
                sP[row * SPS + tx * 4 + j] = p;
                rs += p;
            }
            sRed[row * 16 + tx] = rs;
        }
        __syncthreads();
        if (tid < 64) {
            float rs = 0.f;
#pragma unroll
            for (int c = 0; c < 16; c++) rs += sRed[tid * 16 + c];
            sL[tid] = sL[tid] * sF[tid] + rs;
        }
        __syncthreads();

        // rescale O and accumulate P@V
#pragma unroll
        for (int i = 0; i < 4; i++) {
            float f = sF[ty * 4 + i];
#pragma unroll
            for (int j = 0; j < 8; j++) oacc[i][j] *= f;
        }
#pragma unroll 2
        for (int kj = 0; kj < 64; kj++) {
            float p[4];
#pragma unroll
            for (int i = 0; i < 4; i++) p[i] = sP[(ty * 4 + i) * SPS + kj];
            float4 v0 = *(const float4*)&sV[kj * VSD + tx * 8];
            float4 v1 = *(const float4*)&sV[kj * VSD + tx * 8 + 4];
#pragma unroll
            for (int i = 0; i < 4; i++) {
                oacc[i][0] += p[i] * v0.x;
                oacc[i][1] += p[i] * v0.y;
                oacc[i][2] += p[i] * v0.z;
                oacc[i][3] += p[i] * v0.w;
                oacc[i][4] += p[i] * v1.x;
                oacc[i][5] += p[i] * v1.y;
                oacc[i][6] += p[i] * v1.z;
                oacc[i][7] += p[i] * v1.w;
            }
        }
    }

#pragma unroll
    for (int i = 0; i < 4; i++) {
        int row = ty * 4 + i;
        int t = qb * 64 + row;
        float inv = 1.f / sL[row];
        float4 r0 = make_float4(oacc[i][0] * inv, oacc[i][1] * inv, oacc[i][2] * inv, oacc[i][3] * inv);
        float4 r1 = make_float4(oacc[i][4] * inv, oacc[i][5] * inv, oacc[i][6] * inv, oacc[i][7] * inv);
        float* cp = ctx + (size_t)t * HH + h * HD + tx * 8;
        *(float4*)cp = r0;
        *(float4*)(cp + 4) = r1;
    }
}

// ---------------------------------------------------------------------------
// Router: one warp per token, 16 logits, softmax, top-2, renormalize
// ---------------------------------------------------------------------------
__global__ void router_kernel(const float* __restrict__ h2, const float* __restrict__ gw,
                              int* __restrict__ topi, float* __restrict__ topw) {
    int w = threadIdx.x >> 5, lane = threadIdx.x & 31;
    int t = blockIdx.x * 8 + w;
    const float* hr = h2 + (size_t)t * HH;
    float logits[NE];
#pragma unroll
    for (int e = 0; e < NE; e++) {
        float s = 0.f;
        for (int i = lane; i < HH; i += 32) s += hr[i] * gw[i * NE + e];
#pragma unroll
        for (int d = 16; d; d >>= 1) s += __shfl_xor_sync(0xffffffffu, s, d);
        logits[e] = s;
    }
    if (lane == 0) {
        float mx = -1e30f;
#pragma unroll
        for (int e = 0; e < NE; e++) mx = fmaxf(mx, logits[e]);
        float pe[NE], sum = 0.f;
#pragma unroll
        for (int e = 0; e < NE; e++) { pe[e] = expf(logits[e] - mx); sum += pe[e]; }
        float isum = 1.f / sum;
#pragma unroll
        for (int e = 0; e < NE; e++) pe[e] *= isum;
        int i1 = 0; float p1 = pe[0];
#pragma unroll
        for (int e = 1; e < NE; e++) if (pe[e] > p1) { p1 = pe[e]; i1 = e; }
        int i2 = -1; float p2 = -1.f;
#pragma unroll
        for (int e = 0; e < NE; e++) if (e != i1 && pe[e] > p2) { p2 = pe[e]; i2 = e; }
        float z = 1.f / (p1 + p2);
        topi[2 * t] = i1; topi[2 * t + 1] = i2;
        topw[2 * t] = p1 * z; topw[2 * t + 1] = p2 * z;
    }
}

// ---------------------------------------------------------------------------
// MoE routing bookkeeping
// ---------------------------------------------------------------------------
__global__ void zero_kernel(int* cnt) {
    if (threadIdx.x < NE) cnt[threadIdx.x] = 0;
}
__global__ void count_kernel(const int* __restrict__ topi, int* __restrict__ cnt) {
    int t = blockIdx.x * 256 + threadIdx.x;
    if (t < TT) {
        atomicAdd(&cnt[topi[2 * t]], 1);
        atomicAdd(&cnt[topi[2 * t + 1]], 1);
    }
}
__global__ void scan_kernel(const int* __restrict__ cnt, int* __restrict__ off,
                            int* __restrict__ cur) {
    if (threadIdx.x == 0) {
        int a = 0;
        for (int e = 0; e < NE; e++) { off[e] = a; a += cnt[e]; cur[e] = 0; }
    }
}
__global__ void scatter_kernel(const int* __restrict__ topi, const int* __restrict__ off,
                               int* __restrict__ cur, int* __restrict__ stok,
                               int* __restrict__ sof) {
    int t = blockIdx.x * 256 + threadIdx.x;
    if (t < TT) {
#pragma unroll
        for (int k = 0; k < TOPK; k++) {
            int e = topi[2 * t + k];
            int p = atomicAdd(&cur[e], 1);
            int s = off[e] + p;
            stok[s] = t;
            sof[2 * t + k] = s;
        }
    }
}

// ---------------------------------------------------------------------------
// SiLU(g) * u  (split a [rows, 2*Fdim]-strided buffer)
// ---------------------------------------------------------------------------
__global__ void silu_mul_kernel(const float* __restrict__ in, float* __restrict__ out,
                                int Fdim, int stride, int total) {
    int idx = blockIdx.x * 256 + threadIdx.x;
    if (idx < total) {
        int r = idx / Fdim, f = idx - r * Fdim;
        float gv = in[(size_t)r * stride + f];
        float uv = in[(size_t)r * stride + Fdim + f];
        out[idx] = gv / (1.f + expf(-gv)) * uv;
    }
}

// ---------------------------------------------------------------------------
// MoE combine: out[t] += w0*eout[s0] + w1*eout[s1]   (deterministic order)
// ---------------------------------------------------------------------------
__global__ void combine_kernel(const float* __restrict__ eout, const int* __restrict__ sof,
                               const float* __restrict__ topw, float* __restrict__ out) {
    int t = blockIdx.x;
    int s0 = sof[2 * t], s1 = sof[2 * t + 1];
    float w0 = topw[2 * t], w1 = topw[2 * t + 1];
    const float4* e0 = (const float4*)(eout + (size_t)s0 * HH);
    const float4* e1 = (const float4*)(eout + (size_t)s1 * HH);
    float4* orow = (float4*)(out + (size_t)t * HH);
#pragma unroll
    for (int it = 0; it < 2; it++) {
        int i = threadIdx.x + it * 256;
        float4 a = orow[i], b = e0[i], c = e1[i];
        a.x += w0 * b.x + w1 * c.x;
        a.y += w0 * b.y + w1 * c.y;
        a.z += w0 * b.z + w1 * c.z;
        a.w += w0 * b.w + w1 * c.w;
        orow[i] = a;
    }
}

// ---------------------------------------------------------------------------
// Launch
// ---------------------------------------------------------------------------
extern "C" void kernel_launch(void* const* d_in, const int* in_sizes, int n_in,
                              void* d_out, int out_size) {
    const float* x       = (const float*)d_in[0];
    const float* gamma1  = (const float*)d_in[1];
    const float* gamma2  = (const float*)d_in[2];
    const float* w_qkv   = (const float*)d_in[3];
    const float* w_o     = (const float*)d_in[4];
    const float* gate_w  = (const float*)d_in[5];
    const float* moe_up  = (const float*)d_in[6];
    const float* moe_dn  = (const float*)d_in[7];
    const float* w13     = (const float*)d_in[8];
    const float* wdn     = (const float*)d_in[9];
    float* out = (float*)d_out;

    float *h1, *qkvp, *ctx, *x1, *h2, *gu, *act, *sg, *sact, *topw;
    int *topi, *cnt, *off, *cur, *stok, *sof;
    cudaGetSymbolAddress((void**)&h1, g_h1);
    cudaGetSymbolAddress((void**)&qkvp, g_qkv);
    cudaGetSymbolAddress((void**)&ctx, g_ctx);
    cudaGetSymbolAddress((void**)&x1, g_x1);
    cudaGetSymbolAddress((void**)&h2, g_h2);
    cudaGetSymbolAddress((void**)&gu, g_gu);
    cudaGetSymbolAddress((void**)&act, g_act);
    cudaGetSymbolAddress((void**)&sg, g_sg);
    cudaGetSymbolAddress((void**)&sact, g_sact);
    cudaGetSymbolAddress((void**)&topw, g_topw);
    cudaGetSymbolAddress((void**)&topi, g_topi);
    cudaGetSymbolAddress((void**)&cnt, g_cnt);
    cudaGetSymbolAddress((void**)&off, g_off);
    cudaGetSymbolAddress((void**)&cur, g_cur);
    cudaGetSymbolAddress((void**)&stok, g_stok);
    cudaGetSymbolAddress((void**)&sof, g_sof);

    cudaFuncSetAttribute(sgemm_k<0>, cudaFuncAttributeMaxDynamicSharedMemorySize, GEMM_SMEM_BYTES);
    cudaFuncSetAttribute(sgemm_k<1>, cudaFuncAttributeMaxDynamicSharedMemorySize, GEMM_SMEM_BYTES);
    cudaFuncSetAttribute(sgemm_k<2>, cudaFuncAttributeMaxDynamicSharedMemorySize, GEMM_SMEM_BYTES);
    cudaFuncSetAttribute(sgemm_k<3>, cudaFuncAttributeMaxDynamicSharedMemorySize, GEMM_SMEM_BYTES);

    // 1. h1 = rmsnorm(x, gamma1)
    rmsnorm_kernel<<<TT, 256>>>(x, gamma1, h1);
    // 2. qkv = h1 @ w_qkv
    sgemm_k<0><<<dim3(6144 / 128, TT / 128, 1), 256, GEMM_SMEM_BYTES>>>(
        h1, w_qkv, qkvp, nullptr, TT, 6144, HH, nullptr, nullptr, nullptr);
    // 3. RoPE in place
    rope_kernel<<<TT, 256>>>(qkvp);
    // 4. attention
    cudaFuncSetAttribute(attn_kernel, cudaFuncAttributeMaxDynamicSharedMemorySize,
                         ATTN_SMEM_FLOATS * 4);
    attn_kernel<<<dim3(TT / 64, NHD), 256, ATTN_SMEM_FLOATS * 4>>>(qkvp, ctx);
    // 5. x1 = ctx @ w_o + x
    sgemm_k<1><<<dim3(HH / 128, TT / 128, 1), 256, GEMM_SMEM_BYTES>>>(
        ctx, w_o, x1, x, TT, HH, HH, nullptr, nullptr, nullptr);
    // 6. h2 = rmsnorm(x1, gamma2)
    rmsnorm_kernel<<<TT, 256>>>(x1, gamma2, h2);
    // 7. routing
    router_kernel<<<TT / 8, 256>>>(h2, gate_w, topi, topw);
    zero_kernel<<<1, 32>>>(cnt);
    count_kernel<<<TT / 256, 256>>>(topi, cnt);
    scan_kernel<<<1, 32>>>(cnt, off, cur);
    scatter_kernel<<<TT / 256, 256>>>(topi, off, cur, stok, sof);
    // 8. MoE up (gather): gu[slot] = h2[token] @ moe_up[e]
    sgemm_k<2><<<dim3(2 * FF / 128, TT / 128, NE), 256, GEMM_SMEM_BYTES>>>(
        h2, moe_up, gu, nullptr, TT, 2 * FF, HH, stok, off, cnt);
    // 9. act = silu(g) * u
    silu_mul_kernel<<<(TT * TOPK * FF) / 256, 256>>>(gu, act, FF, 2 * FF, TT * TOPK * FF);
    // 10. shared expert up
    sgemm_k<0><<<dim3(2 * FSH / 128, TT / 128, 1), 256, GEMM_SMEM_BYTES>>>(
        h2, w13, sg, nullptr, TT, 2 * FSH, HH, nullptr, nullptr, nullptr);
    silu_mul_kernel<<<(TT * FSH) / 256, 256>>>(sg, sact, FSH, 2 * FSH, TT * FSH);
    // 11. out = sact @ shared_down + x1
    sgemm_k<1><<<dim3(HH / 128, TT / 128, 1), 256, GEMM_SMEM_BYTES>>>(
        sact, wdn, out, x1, TT, HH, FSH, nullptr, nullptr, nullptr);
    // 12. MoE down: eout[slot] = act[slot] @ moe_down[e]   (reuse gu buffer as eout)
    sgemm_k<3><<<dim3(HH / 128, TT / 128, NE), 256, GEMM_SMEM_BYTES>>>(
        act, moe_dn, gu, nullptr, TT, HH, FF, stok, off, cnt);
    // 13. out[t] += w0*eout[s0] + w1*eout[s1]
    combine_kernel<<<TT, 256>>>(gu, sof, topw, out);
}

// round 13
// speedup vs baseline: 1.0949x; 1.0949x over previous
#include <cuda_runtime.h>
#include <math.h>
#include <stdint.h>

// Problem constants
#define TT   2048
#define HH   2048
#define NHD  16
#define HD   128
#define NE   16
#define TOPK 2
#define FF   1024
#define FSH  4096
#define EPSV 1e-6f

// ---------------------------------------------------------------------------
// Scratch (device globals; allocation-free per harness rules)
// ---------------------------------------------------------------------------
__device__ float g_h1[TT * HH];
__device__ float g_qkv[TT * 3 * HH];
__device__ float g_ctx[TT * HH];
__device__ float g_x1[TT * HH];
__device__ float g_h2[TT * HH];
__device__ float g_gu[TT * TOPK * 2 * FF];   // reused as eout after act
__device__ float g_act[TT * TOPK * FF];
__device__ float g_sg[TT * 2 * FSH];
__device__ float g_sact[TT * FSH];
__device__ int   g_topi[TT * TOPK];
__device__ float g_topw[TT * TOPK];
__device__ int   g_cnt[NE];
__device__ int   g_off[NE];
__device__ int   g_cur[NE];
__device__ int   g_stok[TT * TOPK];
__device__ int   g_sof[TT * TOPK];

// ---------------------------------------------------------------------------
// TF32 helpers
// ---------------------------------------------------------------------------
__device__ __forceinline__ float to_tf32(float x) {
    uint32_t u;
    asm("cvt.rna.tf32.f32 %0, %1;" : "=r"(u) : "f"(x));
    return __uint_as_float(u);
}

__device__ __forceinline__ void tf32_split(float x, uint32_t& hi, uint32_t& lo) {
    float h = to_tf32(x);
    float l = to_tf32(x - h);
    hi = __float_as_uint(h);
    lo = __float_as_uint(l);
}

__device__ __forceinline__ void mma_tf32(float& c0, float& c1, float& c2, float& c3,
                                         uint32_t a0, uint32_t a1, uint32_t a2, uint32_t a3,
                                         uint32_t b0, uint32_t b1) {
    asm volatile(
        "mma.sync.aligned.m16n8k8.row.col.f32.tf32.tf32.f32 "
        "{%0,%1,%2,%3}, {%4,%5,%6,%7}, {%8,%9}, {%0,%1,%2,%3};"
        : "+f"(c0), "+f"(c1), "+f"(c2), "+f"(c3)
        : "r"(a0), "r"(a1), "r"(a2), "r"(a3), "r"(b0), "r"(b1));
}

// ---------------------------------------------------------------------------
// RMSNorm: one block per row
// ---------------------------------------------------------------------------
__global__ void rmsnorm_kernel(const float* __restrict__ x, const float* __restrict__ g,
                               float* __restrict__ o) {
    int t = blockIdx.x;
    const float4* xr = (const float4*)(x + (size_t)t * HH);
    const float4* gr = (const float4*)g;
    float4* orow = (float4*)(o + (size_t)t * HH);
    float4 v[2];
    float ss = 0.f;
#pragma unroll
    for (int it = 0; it < 2; it++) {
        v[it] = xr[threadIdx.x + it * 256];
        ss += v[it].x * v[it].x + v[it].y * v[it].y + v[it].z * v[it].z + v[it].w * v[it].w;
    }
#pragma unroll
    for (int d = 16; d; d >>= 1) ss += __shfl_xor_sync(0xffffffffu, ss, d);
    __shared__ float red[8];
    __shared__ float sscale;
    int w = threadIdx.x >> 5, l = threadIdx.x & 31;
    if (l == 0) red[w] = ss;
    __syncthreads();
    if (threadIdx.x == 0) {
        float s2 = 0.f;
#pragma unroll
        for (int i = 0; i < 8; i++) s2 += red[i];
        sscale = rsqrtf(s2 / (float)HH + EPSV);
    }
    __syncthreads();
    float sc = sscale;
#pragma unroll
    for (int it = 0; it < 2; it++) {
        float4 gv = gr[threadIdx.x + it * 256];
        float4 r;
        r.x = v[it].x * sc * gv.x;
        r.y = v[it].y * sc * gv.y;
        r.z = v[it].z * sc * gv.z;
        r.w = v[it].w * sc * gv.w;
        orow[threadIdx.x + it * 256] = r;
    }
}

// ---------------------------------------------------------------------------
// 3xTF32 tensor-core GEMM, 128x128 CTA tile, K-tile 16, 512 threads
// (16 warps), warp grid 4(m) x 4(n): each warp 32x32 via 2x4 m16n8k8 tiles
// => acc only 32 regs/thread (no spills under 512-thread reg budget).
// smem As[k][m] / Bs[k][n] raw fp32, stride 136 (conflict-free fragment
// loads); tf32 hi/lo split in registers (smem bandwidth stays 4B/elem).
// Register prefetch (one float4/array) + double-buffered smem.
// MODE 0: C = A@B      MODE 1: C = A@B + D
// MODE 2: MoE up (A rows gathered via slot_tok, per-expert B, C by slot)
// MODE 3: MoE down (A/C rows contiguous per-expert slots, per-expert B)
// ---------------------------------------------------------------------------
#define KT 16
#define SST 136   // smem row stride (floats)

template <int MODE>
__global__ void __launch_bounds__(512, 1)
sgemm_k(const float* __restrict__ A, const float* __restrict__ B, float* __restrict__ C,
        const float* __restrict__ D, int M, int N, int Kd,
        const int* __restrict__ slot_tok, const int* __restrict__ off,
        const int* __restrict__ cnt) {
    __shared__ float As[2][KT * SST];
    __shared__ float Bs[2][KT * SST];

    const int tid = threadIdx.x;
    int Me = M, base = 0;
    const float* Bp = B;
    if (MODE >= 2) {
        int e = blockIdx.z;
        Me = cnt[e];
        base = off[e];
        Bp = B + (size_t)e * Kd * N;
    }
    int m0 = blockIdx.y * 128;
    if (m0 >= Me) return;
    int n0 = blockIdx.x * 128;

    // ---- global load mapping (one float4 per thread per array) ----
    int aRow = tid >> 2;           // 0..127
    int aSel = tid & 3;            // which 4-k quarter
    bool aValid = (m0 + aRow) < Me;
    size_t aIdx = 0;
    if (MODE == 2) {
        aIdx = aValid ? (size_t)slot_tok[base + m0 + aRow] * Kd : 0;
    } else if (MODE == 3) {
        aIdx = (size_t)(base + m0 + aRow) * Kd;
    } else {
        aIdx = (size_t)(m0 + aRow) * Kd;
    }
    int bRow = tid >> 5;           // 0..15
    int bC4 = (tid & 31) << 2;     // 0..124
    const float* bPtr = Bp + (size_t)bRow * N + n0 + bC4;

    // ---- mma thread mapping ----
    const int lane = tid & 31;
    const int g = lane >> 2;       // group id 0..7
    const int tig = lane & 3;      // thread in group 0..3
    const int wid = tid >> 5;      // 0..15
    const int warp_m = wid >> 2;   // 0..3
    const int warp_n = wid & 3;    // 0..3

    float acc[2][4][4];
#pragma unroll
    for (int i = 0; i < 2; i++)
#pragma unroll
        for (int j = 0; j < 4; j++)
#pragma unroll
            for (int c = 0; c < 4; c++) acc[i][j][c] = 0.f;

    // ---- prologue: tile 0 ----
    float4 av = make_float4(0.f, 0.f, 0.f, 0.f);
    if (aValid) av = *(const float4*)(A + aIdx + aSel * 4);
    float4 bv = *(const float4*)bPtr;
    {
        int ak = aSel * 4;
        As[0][(ak + 0) * SST + aRow] = av.x;
        As[0][(ak + 1) * SST + aRow] = av.y;
        As[0][(ak + 2) * SST + aRow] = av.z;
        As[0][(ak + 3) * SST + aRow] = av.w;
        *(float4*)&Bs[0][bRow * SST + bC4] = bv;
    }
    __syncthreads();

    int buf = 0;
    for (int k0 = 0; k0 < Kd; k0 += KT) {
        int kn = k0 + KT;
        bool more = kn < Kd;
        if (more) {
            if (aValid) av = *(const float4*)(A + aIdx + kn + aSel * 4);
            bv = *(const float4*)(bPtr + (size_t)kn * N);
        }

        // ---- compute 2 k8 steps from smem ----
#pragma unroll
        for (int kk8 = 0; kk8 < KT; kk8 += 8) {
            const float* Ab0 = &As[buf][(kk8 + tig) * SST];
            const float* Ab4 = &As[buf][(kk8 + tig + 4) * SST];
            const float* Bb0 = &Bs[buf][(kk8 + tig) * SST + warp_n * 32];
            const float* Bb4 = &Bs[buf][(kk8 + tig + 4) * SST + warp_n * 32];
            uint32_t bh[8], bl[8];
#pragma unroll
            for (int j = 0; j < 4; j++) {
                tf32_split(Bb0[j * 8 + g], bh[2 * j],     bl[2 * j]);
                tf32_split(Bb4[j * 8 + g], bh[2 * j + 1], bl[2 * j + 1]);
            }
#pragma unroll
            for (int i = 0; i < 2; i++) {
                int m = warp_m * 32 + i * 16 + g;
                uint32_t ah0, al0, ah1, al1, ah2, al2, ah3, al3;
                tf32_split(Ab0[m],     ah0, al0);
                tf32_split(Ab0[m + 8], ah1, al1);
                tf32_split(Ab4[m],     ah2, al2);
                tf32_split(Ab4[m + 8], ah3, al3);
#pragma unroll
                for (int j = 0; j < 4; j++) {
                    mma_tf32(acc[i][j][0], acc[i][j][1], acc[i][j][2], acc[i][j][3],
                             ah0, ah1, ah2, ah3, bl[2 * j], bl[2 * j + 1]);
                    mma_tf32(acc[i][j][0], acc[i][j][1], acc[i][j][2], acc[i][j][3],
                             al0, al1, al2, al3, bh[2 * j], bh[2 * j + 1]);
                    mma_tf32(acc[i][j][0], acc[i][j][1], acc[i][j][2], acc[i][j][3],
                             ah0, ah1, ah2, ah3, bh[2 * j], bh[2 * j + 1]);
                }
            }
        }

        if (more) {
            int nb = buf ^ 1;
            int ak = aSel * 4;
            As[nb][(ak + 0) * SST + aRow] = av.x;
            As[nb][(ak + 1) * SST + aRow] = av.y;
            As[nb][(ak + 2) * SST + aRow] = av.z;
            As[nb][(ak + 3) * SST + aRow] = av.w;
            *(float4*)&Bs[nb][bRow * SST + bC4] = bv;
            __syncthreads();
            buf = nb;
        }
    }

    // ---- epilogue ----
#pragma unroll
    for (int i = 0; i < 2; i++) {
        int r0i = m0 + warp_m * 32 + i * 16 + g;
        int r1i = r0i + 8;
#pragma unroll
        for (int j = 0; j < 4; j++) {
            int col = n0 + warp_n * 32 + j * 8 + 2 * tig;
            if (MODE < 2 || r0i < Me) {
                size_t crow = (MODE >= 2) ? (size_t)(base + r0i) : (size_t)r0i;
                float2 cv = make_float2(acc[i][j][0], acc[i][j][1]);
                if (MODE == 1) {
                    float2 dv = *(const float2*)(D + (size_t)r0i * N + col);
                    cv.x += dv.x; cv.y += dv.y;
                }
                *(float2*)(C + crow * N + col) = cv;
            }
            if (MODE < 2 || r1i < Me) {
                size_t crow = (MODE >= 2) ? (size_t)(base + r1i) : (size_t)r1i;
                float2 cv = make_float2(acc[i][j][2], acc[i][j][3]);
                if (MODE == 1) {
                    float2 dv = *(const float2*)(D + (size_t)r1i * N + col);
                    cv.x += dv.x; cv.y += dv.y;
                }
                *(float2*)(C + crow * N + col) = cv;
            }
        }
    }
}

// ---------------------------------------------------------------------------
// RoPE in-place on q,k inside g_qkv
// ---------------------------------------------------------------------------
__global__ void rope_kernel(float* __restrict__ qkv) {
    int t = blockIdx.x;
    for (int idx = threadIdx.x; idx < NHD * 64; idx += blockDim.x) {
        int h = idx >> 6, i = idx & 63;
        // 10000^(-i/64) = exp2(-i/64 * log2(10000))
        float inv = exp2f(-(float)i * (13.287712379549449f / 64.f));
        float ang = (float)t * inv;
        float c = cosf(ang), s = sinf(ang);
        float* q = qkv + (size_t)t * 6144 + h * HD;
        float* k = q + 2048;
        float q1 = q[i], q2 = q[i + 64];
        q[i] = q1 * c - q2 * s;
        q[i + 64] = q1 * s + q2 * c;
        float k1 = k[i], k2 = k[i + 64];
        k[i] = k1 * c - k2 * s;
        k[i + 64] = k1 * s + k2 * c;
    }
}

// ---------------------------------------------------------------------------
// Flash attention: QK^T via 3xTF32 tensor cores, softmax + PV in fp32 SIMT.
// Block = (64 queries, one head); iterates 64-key tiles. Heavy q-blocks
// scheduled first (qb reversed) for LPT-style balance of triangular work.
// ---------------------------------------------------------------------------
#define QS 132
#define KS 132
#define VSD 132
#define SPS 68
#define ATTN_SMEM_FLOATS (64 * QS + 64 * KS + 64 * VSD + 64 * SPS + 64 * 16 + 3 * 64)

__global__ void __launch_bounds__(256, 1)
attn_kernel(const float* __restrict__ qkv, float* __restrict__ ctx) {
    extern __shared__ float sm[];
    float* sQ = sm;                  // 64 x QS   (q row-major)
    float* sK = sQ + 64 * QS;        // 64 x KS   (k row-major)
    float* sV = sK + 64 * KS;        // 64 x VSD
    float* sP = sV + 64 * VSD;       // 64 x SPS  (scores / probs)
    float* sRed = sP + 64 * SPS;     // 64 x 16
    float* sM = sRed + 64 * 16;
    float* sL = sM + 64;
    float* sF = sL + 64;

    const int tid = threadIdx.x;
    const int qb = (int)gridDim.x - 1 - (int)blockIdx.x;  // heavy blocks first
    const int h = blockIdx.y;
    const int ty = tid >> 4, tx = tid & 15;
    const int lane = tid & 31, g = lane >> 2, tig = lane & 3;
    const int wid = tid >> 5;
    const int wqm = wid >> 1;        // 0..3: QK warp m16-row block
    const int wqn = wid & 1;         // 0..1: QK warp n32-col block
    const float iss = 0.08838834764831845f;  // 1/sqrt(128)

#pragma unroll
    for (int it = 0; it < 8; it++) {
        int idx = it * 256 + tid;
        int r = idx >> 5, c4 = (idx & 31) << 2;
        float4 qv = *(const float4*)(qkv + (size_t)(qb * 64 + r) * 6144 + h * HD + c4);
        *(float4*)&sQ[r * QS + c4] = qv;
    }
    if (tid < 64) { sM[tid] = -1e30f; sL[tid] = 0.f; }

    float oacc[4][8];
#pragma unroll
    for (int i = 0; i < 4; i++)
#pragma unroll
        for (int j = 0; j < 8; j++) oacc[i][j] = 0.f;

    for (int kb = 0; kb <= qb; kb++) {
        __syncthreads();
#pragma unroll
        for (int it = 0; it < 8; it++) {
            int idx = it * 256 + tid;
            int r = idx >> 5, c4 = (idx & 31) << 2;
            const float* bp = qkv + (size_t)(kb * 64 + r) * 6144 + 2048 + h * HD + c4;
            float4 kv = *(const float4*)bp;
            *(float4*)&sK[r * KS + c4] = kv;
            float4 vv = *(const float4*)(bp + 2048);
            *(float4*)&sV[r * VSD + c4] = vv;
        }
        __syncthreads();

        // ---- S = Q @ K^T via 3xTF32 mma; each warp computes 16x32 ----
        float qacc[4][4];
#pragma unroll
        for (int j = 0; j < 4; j++)
#pragma unroll
            for (int c = 0; c < 4; c++) qacc[j][c] = 0.f;

#pragma unroll 4
        for (int d8 = 0; d8 < HD; d8 += 8) {
            uint32_t ah0, al0, ah1, al1, ah2, al2, ah3, al3;
            tf32_split(sQ[(wqm * 16 + g) * QS + d8 + tig],     ah0, al0);
            tf32_split(sQ[(wqm * 16 + g + 8) * QS + d8 + tig], ah1, al1);
            tf32_split(sQ[(wqm * 16 + g) * QS + d8 + tig + 4],     ah2, al2);
            tf32_split(sQ[(wqm * 16 + g + 8) * QS + d8 + tig + 4], ah3, al3);
#pragma unroll
            for (int j = 0; j < 4; j++) {
                uint32_t bh0, bl0, bh1, bl1;
                int krow = wqn * 32 + j * 8 + g;
                tf32_split(sK[krow * KS + d8 + tig],     bh0, bl0);
                tf32_split(sK[krow * KS + d8 + tig + 4], bh1, bl1);
                mma_tf32(qacc[j][0], qacc[j][1], qacc[j][2], qacc[j][3],
                         ah0, ah1, ah2, ah3, bl0, bl1);
                mma_tf32(qacc[j][0], qacc[j][1], qacc[j][2], qacc[j][3],
                         al0, al1, al2, al3, bh0, bh1);
                mma_tf32(qacc[j][0], qacc[j][1], qacc[j][2], qacc[j][3],
                         ah0, ah1, ah2, ah3, bh0, bh1);
            }
        }

        // write raw S to sP (mma C layout: rows g/g+8, cols 2tig/2tig+1)
#pragma unroll
        for (int j = 0; j < 4; j++) {
            int col = wqn * 32 + j * 8 + 2 * tig;
            *(float2*)&sP[(wqm * 16 + g) * SPS + col] =
                make_float2(qacc[j][0], qacc[j][1]);
            *(float2*)&sP[(wqm * 16 + g + 8) * SPS + col] =
                make_float2(qacc[j][2], qacc[j][3]);
        }
        __syncthreads();

        // ---- read 4x4 ownership block; scale + causal mask ----
        float sacc[4][4];
#pragma unroll
        for (int i = 0; i < 4; i++)
#pragma unroll
            for (int j = 0; j < 4; j++)
                sacc[i][j] = sP[(ty * 4 + i) * SPS + tx * 4 + j];

        if (kb == qb) {
#pragma unroll
            for (int i = 0; i < 4; i++) {
                int qi = ty * 4 + i;
#pragma unroll
                for (int j = 0; j < 4; j++) {
                    int kj = tx * 4 + j;
                    float s = sacc[i][j] * iss;
                    sacc[i][j] = (kj > qi) ? -1e30f : s;
                }
            }
        } else {
#pragma unroll
            for (int i = 0; i < 4; i++)
#pragma unroll
                for (int j = 0; j < 4; j++) sacc[i][j] *= iss;
        }

        // row max
#pragma unroll
        for (int i = 0; i < 4; i++) {
            float lm = fmaxf(fmaxf(sacc[i][0], sacc[i][1]), fmaxf(sacc[i][2], sacc[i][3]));
            sRed[(ty * 4 + i) * 16 + tx] = lm;
        }
        __syncthreads();
        if (tid < 64) {
            float m_old = sM[tid];
            float tm = -1e30f;
#pragma unroll
            for (int c = 0; c < 16; c++) tm = fmaxf(tm, sRed[tid * 16 + c]);
            float m_new = fmaxf(m_old, tm);
            sM[tid] = m_new;
            sF[tid] = expf(m_old - m_new);
        }
        __syncthreads();

        // P = exp(S - m), row sums
#pragma unroll
        for (int i = 0; i < 4; i++) {
            int row = ty * 4 + i;
            float m = sM[row];
            float rs = 0.f;
#pragma unroll
            for (int j = 0; j < 4; j++) {
                float p = expf(sacc[i][j] - m);
                sP[row * SPS + tx * 4 + j] = p;
                rs += p;
            }
            sRed[row * 16 + tx] = rs;
        }
        __syncthreads();
        if (tid < 64) {
            float rs = 0.f;
#pragma unroll
            for (int c = 0; c < 16; c++) rs += sRed[tid * 16 + c];
            sL[tid] = sL[tid] * sF[tid] + rs;
        }
        __syncthreads();

        // rescale O and accumulate P@V
#pragma unroll
        for (int i = 0; i < 4; i++) {
            float f = sF[ty * 4 + i];
#pragma unroll
            for (int j = 0; j < 8; j++) oacc[i][j] *= f;
        }
#pragma unroll 2
        for (int kj = 0; kj < 64; kj++) {
            float p[4];
#pragma unroll
            for (int i = 0; i < 4; i++) p[i] = sP[(ty * 4 + i) * SPS + kj];
            float4 v0 = *(const float4*)&sV[kj * VSD + tx * 8];
            float4 v1 = *(const float4*)&sV[kj * VSD + tx * 8 + 4];
#pragma unroll
            for (int i = 0; i < 4; i++) {
                oacc[i][0] += p[i] * v0.x;
                oacc[i][1] += p[i] * v0.y;
                oacc[i][2] += p[i] * v0.z;
                oacc[i][3] += p[i] * v0.w;
                oacc[i][4] += p[i] * v1.x;
                oacc[i][5] += p[i] * v1.y;
                oacc[i][6] += p[i] * v1.z;
                oacc[i][7] += p[i] * v1.w;
            }
        }
    }

#pragma unroll
    for (int i = 0; i < 4; i++) {
        int row = ty * 4 + i;
        int t = qb * 64 + row;
        float inv = 1.f / sL[row];
        float4 r0 = make_float4(oacc[i][0] * inv, oacc[i][1] * inv, oacc[i][2] * inv, oacc[i][3] * inv);
        float4 r1 = make_float4(oacc[i][4] * inv, oacc[i][5] * inv, oacc[i][6] * inv, oacc[i][7] * inv);
        float* cp = ctx + (size_t)t * HH + h * HD + tx * 8;
        *(float4*)cp = r0;
        *(float4*)(cp + 4) = r1;
    }
}

// ---------------------------------------------------------------------------
// Router: one warp per token, 16 logits, softmax, top-2, renormalize
// ---------------------------------------------------------------------------
__global__ void router_kernel(const float* __restrict__ h2, const float* __restrict__ gw,
                              int* __restrict__ topi, float* __restrict__ topw) {
    int w = threadIdx.x >> 5, lane = threadIdx.x & 31;
    int t = blockIdx.x * 8 + w;
    const float* hr = h2 + (size_t)t * HH;
    float logits[NE];
#pragma unroll
    for (int e = 0; e < NE; e++) {
        float s = 0.f;
        for (int i = lane; i < HH; i += 32) s += hr[i] * gw[i * NE + e];
#pragma unroll
        for (int d = 16; d; d >>= 1) s += __shfl_xor_sync(0xffffffffu, s, d);
        logits[e] = s;
    }
    if (lane == 0) {
        float mx = -1e30f;
#pragma unroll
        for (int e = 0; e < NE; e++) mx = fmaxf(mx, logits[e]);
        float pe[NE], sum = 0.f;
#pragma unroll
        for (int e = 0; e < NE; e++) { pe[e] = expf(logits[e] - mx); sum += pe[e]; }
        float isum = 1.f / sum;
#pragma unroll
        for (int e = 0; e < NE; e++) pe[e] *= isum;
        int i1 = 0; float p1 = pe[0];
#pragma unroll
        for (int e = 1; e < NE; e++) if (pe[e] > p1) { p1 = pe[e]; i1 = e; }
        int i2 = -1; float p2 = -1.f;
#pragma unroll
        for (int e = 0; e < NE; e++) if (e != i1 && pe[e] > p2) { p2 = pe[e]; i2 = e; }
        float z = 1.f / (p1 + p2);
        topi[2 * t] = i1; topi[2 * t + 1] = i2;
        topw[2 * t] = p1 * z; topw[2 * t + 1] = p2 * z;
    }
}

// ---------------------------------------------------------------------------
// MoE routing bookkeeping
// ---------------------------------------------------------------------------
__global__ void zero_kernel(int* cnt) {
    if (threadIdx.x < NE) cnt[threadIdx.x] = 0;
}
__global__ void count_kernel(const int* __restrict__ topi, int* __restrict__ cnt) {
    int t = blockIdx.x * 256 + threadIdx.x;
    if (t < TT) {
        atomicAdd(&cnt[topi[2 * t]], 1);
        atomicAdd(&cnt[topi[2 * t + 1]], 1);
    }
}
__global__ void scan_kernel(const int* __restrict__ cnt, int* __restrict__ off,
                            int* __restrict__ cur) {
    if (threadIdx.x == 0) {
        int a = 0;
        for (int e = 0; e < NE; e++) { off[e] = a; a += cnt[e]; cur[e] = 0; }
    }
}
__global__ void scatter_kernel(const int* __restrict__ topi, const int* __restrict__ off,
                               int* __restrict__ cur, int* __restrict__ stok,
                               int* __restrict__ sof) {
    int t = blockIdx.x * 256 + threadIdx.x;
    if (t < TT) {
#pragma unroll
        for (int k = 0; k < TOPK; k++) {
            int e = topi[2 * t + k];
            int p = atomicAdd(&cur[e], 1);
            int s = off[e] + p;
            stok[s] = t;
            sof[2 * t + k] = s;
        }
    }
}

// ---------------------------------------------------------------------------
// SiLU(g) * u  (split a [rows, 2*Fdim]-strided buffer)
// ---------------------------------------------------------------------------
__global__ void silu_mul_kernel(const float* __restrict__ in, float* __restrict__ out,
                                int Fdim, int stride, int total) {
    int idx = blockIdx.x * 256 + threadIdx.x;
    if (idx < total) {
        int r = idx / Fdim, f = idx - r * Fdim;
        float gv = in[(size_t)r * stride + f];
        float uv = in[(size_t)r * stride + Fdim + f];
        out[idx] = gv / (1.f + expf(-gv)) * uv;
    }
}

// ---------------------------------------------------------------------------
// MoE combine: out[t] += w0*eout[s0] + w1*eout[s1]   (deterministic order)
// ---------------------------------------------------------------------------
__global__ void combine_kernel(const float* __restrict__ eout, const int* __restrict__ sof,
                               const float* __restrict__ topw, float* __restrict__ out) {
    int t = blockIdx.x;
    int s0 = sof[2 * t], s1 = sof[2 * t + 1];
    float w0 = topw[2 * t], w1 = topw[2 * t + 1];
    const float4* e0 = (const float4*)(eout + (size_t)s0 * HH);
    const float4* e1 = (const float4*)(eout + (size_t)s1 * HH);
    float4* orow = (float4*)(out + (size_t)t * HH);
#pragma unroll
    for (int it = 0; it < 2; it++) {
        int i = threadIdx.x + it * 256;
        float4 a = orow[i], b = e0[i], c = e1[i];
        a.x += w0 * b.x + w1 * c.x;
        a.y += w0 * b.y + w1 * c.y;
        a.z += w0 * b.z + w1 * c.z;
        a.w += w0 * b.w + w1 * c.w;
        orow[i] = a;
    }
}

// ---------------------------------------------------------------------------
// Launch
// ---------------------------------------------------------------------------
extern "C" void kernel_launch(void* const* d_in, const int* in_sizes, int n_in,
                              void* d_out, int out_size) {
    const float* x       = (const float*)d_in[0];
    const float* gamma1  = (const float*)d_in[1];
    const float* gamma2  = (const float*)d_in[2];
    const float* w_qkv   = (const float*)d_in[3];
    const float* w_o     = (const float*)d_in[4];
    const float* gate_w  = (const float*)d_in[5];
    const float* moe_up  = (const float*)d_in[6];
    const float* moe_dn  = (const float*)d_in[7];
    const float* w13     = (const float*)d_in[8];
    const float* wdn     = (const float*)d_in[9];
    float* out = (float*)d_out;

    float *h1, *qkvp, *ctx, *x1, *h2, *gu, *act, *sg, *sact, *topw;
    int *topi, *cnt, *off, *cur, *stok, *sof;
    cudaGetSymbolAddress((void**)&h1, g_h1);
    cudaGetSymbolAddress((void**)&qkvp, g_qkv);
    cudaGetSymbolAddress((void**)&ctx, g_ctx);
    cudaGetSymbolAddress((void**)&x1, g_x1);
    cudaGetSymbolAddress((void**)&h2, g_h2);
    cudaGetSymbolAddress((void**)&gu, g_gu);
    cudaGetSymbolAddress((void**)&act, g_act);
    cudaGetSymbolAddress((void**)&sg, g_sg);
    cudaGetSymbolAddress((void**)&sact, g_sact);
    cudaGetSymbolAddress((void**)&topw, g_topw);
    cudaGetSymbolAddress((void**)&topi, g_topi);
    cudaGetSymbolAddress((void**)&cnt, g_cnt);
    cudaGetSymbolAddress((void**)&off, g_off);
    cudaGetSymbolAddress((void**)&cur, g_cur);
    cudaGetSymbolAddress((void**)&stok, g_stok);
    cudaGetSymbolAddress((void**)&sof, g_sof);

    // 1. h1 = rmsnorm(x, gamma1)
    rmsnorm_kernel<<<TT, 256>>>(x, gamma1, h1);
    // 2. qkv = h1 @ w_qkv
    sgemm_k<0><<<dim3(6144 / 128, TT / 128, 1), 512>>>(h1, w_qkv, qkvp, nullptr, TT, 6144, HH,
                                                       nullptr, nullptr, nullptr);
    // 3. RoPE in place
    rope_kernel<<<TT, 256>>>(qkvp);
    // 4. attention
    cudaFuncSetAttribute(attn_kernel, cudaFuncAttributeMaxDynamicSharedMemorySize,
                         ATTN_SMEM_FLOATS * 4);
    attn_kernel<<<dim3(TT / 64, NHD), 256, ATTN_SMEM_FLOATS * 4>>>(qkvp, ctx);
    // 5. x1 = ctx @ w_o + x
    sgemm_k<1><<<dim3(HH / 128, TT / 128, 1), 512>>>(ctx, w_o, x1, x, TT, HH, HH,
                                                     nullptr, nullptr, nullptr);
    // 6. h2 = rmsnorm(x1, gamma2)
    rmsnorm_kernel<<<TT, 256>>>(x1, gamma2, h2);
    // 7. routing
    router_kernel<<<TT / 8, 256>>>(h2, gate_w, topi, topw);
    zero_kernel<<<1, 32>>>(cnt);
    count_kernel<<<TT / 256, 256>>>(topi, cnt);
    scan_kernel<<<1, 32>>>(cnt, off, cur);
    scatter_kernel<<<TT / 256, 256>>>(topi, off, cur, stok, sof);
    // 8. MoE up (gather): gu[slot] = h2[token] @ moe_up[e]
    sgemm_k<2><<<dim3(2 * FF / 128, TT / 128, NE), 512>>>(h2, moe_up, gu, nullptr, TT, 2 * FF, HH,
                                                          stok, off, cnt);
    // 9. act = silu(g) * u
    silu_mul_kernel<<<(TT * TOPK * FF) / 256, 256>>>(gu, act, FF, 2 * FF, TT * TOPK * FF);
    // 10. shared expert up
    sgemm_k<0><<<dim3(2 * FSH / 128, TT / 128, 1), 512>>>(h2, w13, sg, nullptr, TT, 2 * FSH, HH,
                                                          nullptr, nullptr, nullptr);
    silu_mul_kernel<<<(TT * FSH) / 256, 256>>>(sg, sact, FSH, 2 * FSH, TT * FSH);
    // 11. out = sact @ shared_down + x1
    sgemm_k<1><<<dim3(HH / 128, TT / 128, 1), 512>>>(sact, wdn, out, x1, TT, HH, FSH,
                                                     nullptr, nullptr, nullptr);
    // 12. MoE down: eout[slot] = act[slot] @ moe_down[e]   (reuse gu buffer as eout)
    sgemm_k<3><<<dim3(HH / 128, TT / 128, NE), 512>>>(act, moe_dn, gu, nullptr, TT, HH, FF,
                                                      stok, off, cnt);
    // 13. out[t] += w0*eout[s0] + w1*eout[s1]
    combine_kernel<<<TT, 256>>>(gu, sof, topw, out);
}

// round 16
// speedup vs baseline: 1.4090x; 1.2869x over previous
#include <cuda_runtime.h>
#include <math.h>
#include <stdint.h>

// Problem constants
#define TT   2048
#define HH   2048
#define NHD  16
#define HD   128
#define NE   16
#define TOPK 2
#define FF   1024
#define FSH  4096
#define EPSV 1e-6f

// ---------------------------------------------------------------------------
// Scratch (device globals; allocation-free per harness rules)
// ---------------------------------------------------------------------------
__device__ float g_h1[TT * HH];
__device__ float g_qkv[TT * 3 * HH];
__device__ float g_ctx[TT * HH];
__device__ float g_x1[TT * HH];
__device__ float g_h2[TT * HH];
__device__ float g_gu[TT * TOPK * 2 * FF];   // reused as eout after act
__device__ float g_act[TT * TOPK * FF];
__device__ float g_sg[TT * 2 * FSH];
__device__ float g_sact[TT * FSH];
__device__ int   g_topi[TT * TOPK];
__device__ float g_topw[TT * TOPK];
__device__ int   g_cnt[NE];
__device__ int   g_off[NE];
__device__ int   g_cur[NE];
__device__ int   g_stok[TT * TOPK];
__device__ int   g_sof[TT * TOPK];

// ---------------------------------------------------------------------------
// TF32 helpers (attention QK^T still uses these)
// ---------------------------------------------------------------------------
__device__ __forceinline__ float to_tf32(float x) {
    uint32_t u;
    asm("cvt.rna.tf32.f32 %0, %1;" : "=r"(u) : "f"(x));
    return __uint_as_float(u);
}

__device__ __forceinline__ void tf32_split(float x, uint32_t& hi, uint32_t& lo) {
    float h = to_tf32(x);
    float l = to_tf32(x - h);
    hi = __float_as_uint(h);
    lo = __float_as_uint(l);
}

__device__ __forceinline__ void mma_tf32(float& c0, float& c1, float& c2, float& c3,
                                         uint32_t a0, uint32_t a1, uint32_t a2, uint32_t a3,
                                         uint32_t b0, uint32_t b1) {
    asm volatile(
        "mma.sync.aligned.m16n8k8.row.col.f32.tf32.tf32.f32 "
        "{%0,%1,%2,%3}, {%4,%5,%6,%7}, {%8,%9}, {%0,%1,%2,%3};"
        : "+f"(c0), "+f"(c1), "+f"(c2), "+f"(c3)
        : "r"(a0), "r"(a1), "r"(a2), "r"(a3), "r"(b0), "r"(b1));
}

// ---------------------------------------------------------------------------
// bf16 helpers (GEMM path)
// ---------------------------------------------------------------------------
// pack (xe = k-even, xo = k-odd) into hi-word (bf16 of each) and lo-word
// (bf16 of residuals). Low 16 bits hold the k-even element (mma convention).
__device__ __forceinline__ void bf16_split_pack(float xe, float xo,
                                                uint32_t& h, uint32_t& l) {
    asm("cvt.rn.bf16x2.f32 %0, %1, %2;" : "=r"(h) : "f"(xo), "f"(xe));
    float he = __uint_as_float(h << 16);
    float ho = __uint_as_float(h & 0xFFFF0000u);
    asm("cvt.rn.bf16x2.f32 %0, %1, %2;" : "=r"(l) : "f"(xo - ho), "f"(xe - he));
}

__device__ __forceinline__ void mma_bf16(float& c0, float& c1, float& c2, float& c3,
                                         uint32_t a0, uint32_t a1, uint32_t a2, uint32_t a3,
                                         uint32_t b0, uint32_t b1) {
    asm volatile(
        "mma.sync.aligned.m16n8k16.row.col.f32.bf16.bf16.f32 "
        "{%0,%1,%2,%3}, {%4,%5,%6,%7}, {%8,%9}, {%0,%1,%2,%3};"
        : "+f"(c0), "+f"(c1), "+f"(c2), "+f"(c3)
        : "r"(a0), "r"(a1), "r"(a2), "r"(a3), "r"(b0), "r"(b1));
}

// ---------------------------------------------------------------------------
// RMSNorm: one block per row
// ---------------------------------------------------------------------------
__global__ void rmsnorm_kernel(const float* __restrict__ x, const float* __restrict__ g,
                               float* __restrict__ o) {
    int t = blockIdx.x;
    const float4* xr = (const float4*)(x + (size_t)t * HH);
    const float4* gr = (const float4*)g;
    float4* orow = (float4*)(o + (size_t)t * HH);
    float4 v[2];
    float ss = 0.f;
#pragma unroll
    for (int it = 0; it < 2; it++) {
        v[it] = xr[threadIdx.x + it * 256];
        ss += v[it].x * v[it].x + v[it].y * v[it].y + v[it].z * v[it].z + v[it].w * v[it].w;
    }
#pragma unroll
    for (int d = 16; d; d >>= 1) ss += __shfl_xor_sync(0xffffffffu, ss, d);
    __shared__ float red[8];
    __shared__ float sscale;
    int w = threadIdx.x >> 5, l = threadIdx.x & 31;
    if (l == 0) red[w] = ss;
    __syncthreads();
    if (threadIdx.x == 0) {
        float s2 = 0.f;
#pragma unroll
        for (int i = 0; i < 8; i++) s2 += red[i];
        sscale = rsqrtf(s2 / (float)HH + EPSV);
    }
    __syncthreads();
    float sc = sscale;
#pragma unroll
    for (int it = 0; it < 2; it++) {
        float4 gv = gr[threadIdx.x + it * 256];
        float4 r;
        r.x = v[it].x * sc * gv.x;
        r.y = v[it].y * sc * gv.y;
        r.z = v[it].z * sc * gv.z;
        r.w = v[it].w * sc * gv.w;
        orow[threadIdx.x + it * 256] = r;
    }
}

// ---------------------------------------------------------------------------
// 3-product split-bf16 tensor-core GEMM (fp32-accurate to ~2^-17).
// 128x128 CTA tile, K-tile 16 (one m16n8k16 step), 512 threads (16 warps),
// warp grid 4(m) x 4(n), each warp 32x32 via 2x4 m16n8k16 tiles.
// smem holds PRE-SPLIT packed bf16x2 hi/lo words, [m][kw] / [n][kw] layout,
// row stride 12 words (g*12+tig all-distinct mod 32: conflict-free frags).
// smem traffic = 4B per fp32 element (hi word + lo word per 2 elements).
// acc += Ahi*Blo + Alo*Bhi + Ahi*Bhi. Register prefetch + double buffering.
// MODE 0: C = A@B      MODE 1: C = A@B + D
// MODE 2: MoE up (A rows gathered via slot_tok, per-expert B, C by slot)
// MODE 3: MoE down (A/C rows contiguous per-expert slots, per-expert B)
// ---------------------------------------------------------------------------
#define KT 16
#define AST 12   // smem row stride (u32 words; 8 data + 4 pad)

template <int MODE>
__global__ void __launch_bounds__(512, 1)
sgemm_k(const float* __restrict__ A, const float* __restrict__ B, float* __restrict__ C,
        const float* __restrict__ D, int M, int N, int Kd,
        const int* __restrict__ slot_tok, const int* __restrict__ off,
        const int* __restrict__ cnt) {
    // [buf][ {Ah, Al, Bh, Bl} ][128 * AST]   = 2*4*1536*4 = 48 KB
    __shared__ uint32_t smem_[2][4][128 * AST];

    const int tid = threadIdx.x;
    int Me = M, base = 0;
    const float* Bp = B;
    if (MODE >= 2) {
        int e = blockIdx.z;
        Me = cnt[e];
        base = off[e];
        Bp = B + (size_t)e * Kd * N;
    }
    int m0 = blockIdx.y * 128;
    if (m0 >= Me) return;
    int n0 = blockIdx.x * 128;

    // ---- global load mapping ----
    // A: 128 rows x 16 k; 4 threads/row, one float4 (4 consecutive k) each
    int aRow = tid >> 2;           // 0..127
    int aKw = (tid & 3) * 2;       // word base 0,2,4,6
    bool aValid = (m0 + aRow) < Me;
    size_t aIdx = 0;
    if (MODE == 2) {
        aIdx = aValid ? (size_t)slot_tok[base + m0 + aRow] * Kd : 0;
    } else if (MODE == 3) {
        aIdx = (size_t)(base + m0 + aRow) * Kd;
    } else {
        aIdx = (size_t)(m0 + aRow) * Kd;
    }
    const int aK = aKw * 2;        // k base 0,4,8,12
    // B: 16 k x 128 n; thread handles k-pair (2kp, 2kp+1) x 2 n columns
    int kp = tid >> 6;             // 0..7
    int nn = (tid & 63) * 2;       // 0..126
    const float* bPtr0 = Bp + (size_t)(2 * kp) * N + n0 + nn;
    const float* bPtr1 = bPtr0 + N;

    // ---- mma thread mapping ----
    const int lane = tid & 31;
    const int g = lane >> 2;       // group id 0..7
    const int tig = lane & 3;      // thread in group 0..3
    const int wid = tid >> 5;      // 0..15
    const int warp_m = wid >> 2;   // 0..3
    const int warp_n = wid & 3;    // 0..3

    float acc[2][4][4];
#pragma unroll
    for (int i = 0; i < 2; i++)
#pragma unroll
        for (int j = 0; j < 4; j++)
#pragma unroll
            for (int c = 0; c < 4; c++) acc[i][j][c] = 0.f;

    // ---- prologue: load + convert tile 0 into buffer 0 ----
    float4 av = make_float4(0.f, 0.f, 0.f, 0.f);
    if (aValid) av = *(const float4*)(A + aIdx + aK);
    float2 bv0 = *(const float2*)bPtr0;
    float2 bv1 = *(const float2*)bPtr1;
    {
        uint32_t* Ah = smem_[0][0];
        uint32_t* Al = smem_[0][1];
        uint32_t* Bh = smem_[0][2];
        uint32_t* Bl = smem_[0][3];
        uint32_t h0, l0, h1, l1;
        bf16_split_pack(av.x, av.y, h0, l0);
        bf16_split_pack(av.z, av.w, h1, l1);
        Ah[aRow * AST + aKw] = h0;
        Ah[aRow * AST + aKw + 1] = h1;
        Al[aRow * AST + aKw] = l0;
        Al[aRow * AST + aKw + 1] = l1;
        bf16_split_pack(bv0.x, bv1.x, h0, l0);   // column nn, k-pair
        bf16_split_pack(bv0.y, bv1.y, h1, l1);   // column nn+1
        Bh[nn * AST + kp] = h0;
        Bh[(nn + 1) * AST + kp] = h1;
        Bl[nn * AST + kp] = l0;
        Bl[(nn + 1) * AST + kp] = l1;
    }
    __syncthreads();

    int buf = 0;
    for (int k0 = 0; k0 < Kd; k0 += KT) {
        int kn = k0 + KT;
        bool more = kn < Kd;
        if (more) {
            if (aValid) av = *(const float4*)(A + aIdx + kn + aK);
            bv0 = *(const float2*)(bPtr0 + (size_t)kn * N);
            bv1 = *(const float2*)(bPtr1 + (size_t)kn * N);
        }

        // ---- one m16n8k16 step from packed smem ----
        {
            const uint32_t* Ah = smem_[buf][0];
            const uint32_t* Al = smem_[buf][1];
            const uint32_t* Bh = smem_[buf][2];
            const uint32_t* Bl = smem_[buf][3];
            uint32_t bh[8], bl[8];
#pragma unroll
            for (int j = 0; j < 4; j++) {
                int nb = (warp_n * 32 + j * 8 + g) * AST;
                bh[2 * j] = Bh[nb + tig];
                bh[2 * j + 1] = Bh[nb + tig + 4];
                bl[2 * j] = Bl[nb + tig];
                bl[2 * j + 1] = Bl[nb + tig + 4];
            }
#pragma unroll
            for (int i = 0; i < 2; i++) {
                int mb = (warp_m * 32 + i * 16 + g) * AST;
                int mb8 = mb + 8 * AST;
                uint32_t ah0 = Ah[mb + tig];
                uint32_t ah1 = Ah[mb8 + tig];
                uint32_t ah2 = Ah[mb + tig + 4];
                uint32_t ah3 = Ah[mb8 + tig + 4];
                uint32_t al0 = Al[mb + tig];
                uint32_t al1 = Al[mb8 + tig];
                uint32_t al2 = Al[mb + tig + 4];
                uint32_t al3 = Al[mb8 + tig + 4];
#pragma unroll
                for (int j = 0; j < 4; j++) {
                    mma_bf16(acc[i][j][0], acc[i][j][1], acc[i][j][2], acc[i][j][3],
                             ah0, ah1, ah2, ah3, bl[2 * j], bl[2 * j + 1]);
                    mma_bf16(acc[i][j][0], acc[i][j][1], acc[i][j][2], acc[i][j][3],
                             al0, al1, al2, al3, bh[2 * j], bh[2 * j + 1]);
                    mma_bf16(acc[i][j][0], acc[i][j][1], acc[i][j][2], acc[i][j][3],
                             ah0, ah1, ah2, ah3, bh[2 * j], bh[2 * j + 1]);
                }
            }
        }

        if (more) {
            int nb = buf ^ 1;
            uint32_t* Ah = smem_[nb][0];
            uint32_t* Al = smem_[nb][1];
            uint32_t* Bh = smem_[nb][2];
            uint32_t* Bl = smem_[nb][3];
            uint32_t h0, l0, h1, l1;
            bf16_split_pack(av.x, av.y, h0, l0);
            bf16_split_pack(av.z, av.w, h1, l1);
            Ah[aRow * AST + aKw] = h0;
            Ah[aRow * AST + aKw + 1] = h1;
            Al[aRow * AST + aKw] = l0;
            Al[aRow * AST + aKw + 1] = l1;
            bf16_split_pack(bv0.x, bv1.x, h0, l0);
            bf16_split_pack(bv0.y, bv1.y, h1, l1);
            Bh[nn * AST + kp] = h0;
            Bh[(nn + 1) * AST + kp] = h1;
            Bl[nn * AST + kp] = l0;
            Bl[(nn + 1) * AST + kp] = l1;
            __syncthreads();
            buf = nb;
        }
    }

    // ---- epilogue (m16n8k16 C layout == m16n8k8: rows g/g+8, cols 2tig) ----
#pragma unroll
    for (int i = 0; i < 2; i++) {
        int r0i = m0 + warp_m * 32 + i * 16 + g;
        int r1i = r0i + 8;
#pragma unroll
        for (int j = 0; j < 4; j++) {
            int col = n0 + warp_n * 32 + j * 8 + 2 * tig;
            if (MODE < 2 || r0i < Me) {
                size_t crow = (MODE >= 2) ? (size_t)(base + r0i) : (size_t)r0i;
                float2 cv = make_float2(acc[i][j][0], acc[i][j][1]);
                if (MODE == 1) {
                    float2 dv = *(const float2*)(D + (size_t)r0i * N + col);
                    cv.x += dv.x; cv.y += dv.y;
                }
                *(float2*)(C + crow * N + col) = cv;
            }
            if (MODE < 2 || r1i < Me) {
                size_t crow = (MODE >= 2) ? (size_t)(base + r1i) : (size_t)r1i;
                float2 cv = make_float2(acc[i][j][2], acc[i][j][3]);
                if (MODE == 1) {
                    float2 dv = *(const float2*)(D + (size_t)r1i * N + col);
                    cv.x += dv.x; cv.y += dv.y;
                }
                *(float2*)(C + crow * N + col) = cv;
            }
        }
    }
}

// ---------------------------------------------------------------------------
// RoPE in-place on q,k inside g_qkv
// ---------------------------------------------------------------------------
__global__ void rope_kernel(float* __restrict__ qkv) {
    int t = blockIdx.x;
    for (int idx = threadIdx.x; idx < NHD * 64; idx += blockDim.x) {
        int h = idx >> 6, i = idx & 63;
        // 10000^(-i/64) = exp2(-i/64 * log2(10000))
        float inv = exp2f(-(float)i * (13.287712379549449f / 64.f));
        float ang = (float)t * inv;
        float c = cosf(ang), s = sinf(ang);
        float* q = qkv + (size_t)t * 6144 + h * HD;
        float* k = q + 2048;
        float q1 = q[i], q2 = q[i + 64];
        q[i] = q1 * c - q2 * s;
        q[i + 64] = q1 * s + q2 * c;
        float k1 = k[i], k2 = k[i + 64];
        k[i] = k1 * c - k2 * s;
        k[i + 64] = k1 * s + k2 * c;
    }
}

// ---------------------------------------------------------------------------
// Flash attention: QK^T via 3xTF32 tensor cores, softmax + PV in fp32 SIMT.
// Block = (64 queries, one head); iterates 64-key tiles. Heavy q-blocks
// scheduled first (qb reversed) for LPT-style balance of triangular work.
// ---------------------------------------------------------------------------
#define QS 132
#define KS 132
#define VSD 132
#define SPS 68
#define ATTN_SMEM_FLOATS (64 * QS + 64 * KS + 64 * VSD + 64 * SPS + 64 * 16 + 3 * 64)

__global__ void __launch_bounds__(256, 1)
attn_kernel(const float* __restrict__ qkv, float* __restrict__ ctx) {
    extern __shared__ float sm[];
    float* sQ = sm;                  // 64 x QS   (q row-major)
    float* sK = sQ + 64 * QS;        // 64 x KS   (k row-major)
    float* sV = sK + 64 * KS;        // 64 x VSD
    float* sP = sV + 64 * VSD;       // 64 x SPS  (scores / probs)
    float* sRed = sP + 64 * SPS;     // 64 x 16
    float* sM = sRed + 64 * 16;
    float* sL = sM + 64;
    float* sF = sL + 64;

    const int tid = threadIdx.x;
    const int qb = (int)gridDim.x - 1 - (int)blockIdx.x;  // heavy blocks first
    const int h = blockIdx.y;
    const int ty = tid >> 4, tx = tid & 15;
    const int lane = tid & 31, g = lane >> 2, tig = lane & 3;
    const int wid = tid >> 5;
    const int wqm = wid >> 1;        // 0..3: QK warp m16-row block
    const int wqn = wid & 1;         // 0..1: QK warp n32-col block
    const float iss = 0.08838834764831845f;  // 1/sqrt(128)

#pragma unroll
    for (int it = 0; it < 8; it++) {
        int idx = it * 256 + tid;
        int r = idx >> 5, c4 = (idx & 31) << 2;
        float4 qv = *(const float4*)(qkv + (size_t)(qb * 64 + r) * 6144 + h * HD + c4);
        *(float4*)&sQ[r * QS + c4] = qv;
    }
    if (tid < 64) { sM[tid] = -1e30f; sL[tid] = 0.f; }

    float oacc[4][8];
#pragma unroll
    for (int i = 0; i < 4; i++)
#pragma unroll
        for (int j = 0; j < 8; j++) oacc[i][j] = 0.f;

    for (int kb = 0; kb <= qb; kb++) {
        __syncthreads();
#pragma unroll
        for (int it = 0; it < 8; it++) {
            int idx = it * 256 + tid;
            int r = idx >> 5, c4 = (idx & 31) << 2;
            const float* bp = qkv + (size_t)(kb * 64 + r) * 6144 + 2048 + h * HD + c4;
            float4 kv = *(const float4*)bp;
            *(float4*)&sK[r * KS + c4] = kv;
            float4 vv = *(const float4*)(bp + 2048);
            *(float4*)&sV[r * VSD + c4] = vv;
        }
        __syncthreads();

        // ---- S = Q @ K^T via 3xTF32 mma; each warp computes 16x32 ----
        float qacc[4][4];
#pragma unroll
        for (int j = 0; j < 4; j++)
#pragma unroll
            for (int c = 0; c < 4; c++) qacc[j][c] = 0.f;

#pragma unroll 4
        for (int d8 = 0; d8 < HD; d8 += 8) {
            uint32_t ah0, al0, ah1, al1, ah2, al2, ah3, al3;
            tf32_split(sQ[(wqm * 16 + g) * QS + d8 + tig],     ah0, al0);
            tf32_split(sQ[(wqm * 16 + g + 8) * QS + d8 + tig], ah1, al1);
            tf32_split(sQ[(wqm * 16 + g) * QS + d8 + tig + 4],     ah2, al2);
            tf32_split(sQ[(wqm * 16 + g + 8) * QS + d8 + tig + 4], ah3, al3);
#pragma unroll
            for (int j = 0; j < 4; j++) {
                uint32_t bh0, bl0, bh1, bl1;
                int krow = wqn * 32 + j * 8 + g;
                tf32_split(sK[krow * KS + d8 + tig],     bh0, bl0);
                tf32_split(sK[krow * KS + d8 + tig + 4], bh1, bl1);
                mma_tf32(qacc[j][0], qacc[j][1], qacc[j][2], qacc[j][3],
                         ah0, ah1, ah2, ah3, bl0, bl1);
                mma_tf32(qacc[j][0], qacc[j][1], qacc[j][2], qacc[j][3],
                         al0, al1, al2, al3, bh0, bh1);
                mma_tf32(qacc[j][0], qacc[j][1], qacc[j][2], qacc[j][3],
                         ah0, ah1, ah2, ah3, bh0, bh1);
            }
        }

        // write raw S to sP (mma C layout: rows g/g+8, cols 2tig/2tig+1)
#pragma unroll
        for (int j = 0; j < 4; j++) {
            int col = wqn * 32 + j * 8 + 2 * tig;
            *(float2*)&sP[(wqm * 16 + g) * SPS + col] =
                make_float2(qacc[j][0], qacc[j][1]);
            *(float2*)&sP[(wqm * 16 + g + 8) * SPS + col] =
                make_float2(qacc[j][2], qacc[j][3]);
        }
        __syncthreads();

        // ---- read 4x4 ownership block; scale + causal mask ----
        float sacc[4][4];
#pragma unroll
        for (int i = 0; i < 4; i++)
#pragma unroll
            for (int j = 0; j < 4; j++)
                sacc[i][j] = sP[(ty * 4 + i) * SPS + tx * 4 + j];

        if (kb == qb) {
#pragma unroll
            for (int i = 0; i < 4; i++) {
                int qi = ty * 4 + i;
#pragma unroll
                for (int j = 0; j < 4; j++) {
                    int kj = tx * 4 + j;
                    float s = sacc[i][j] * iss;
                    sacc[i][j] = (kj > qi) ? -1e30f : s;
                }
            }
        } else {
#pragma unroll
            for (int i = 0; i < 4; i++)
#pragma unroll
                for (int j = 0; j < 4; j++) sacc[i][j] *= iss;
        }

        // row max
#pragma unroll
        for (int i = 0; i < 4; i++) {
            float lm = fmaxf(fmaxf(sacc[i][0], sacc[i][1]), fmaxf(sacc[i][2], sacc[i][3]));
            sRed[(ty * 4 + i) * 16 + tx] = lm;
        }
        __syncthreads();
        if (tid < 64) {
            float m_old = sM[tid];
            float tm = -1e30f;
#pragma unroll
            for (int c = 0; c < 16; c++) tm = fmaxf(tm, sRed[tid * 16 + c]);
            float m_new = fmaxf(m_old, tm);
            sM[tid] = m_new;
            sF[tid] = expf(m_old - m_new);
        }
        __syncthreads();

        // P = exp(S - m), row sums
#pragma unroll
        for (int i = 0; i < 4; i++) {
            int row = ty * 4 + i;
            float m = sM[row];
            float rs = 0.f;
#pragma unroll
            for (int j = 0; j < 4; j++) {
                float p = expf(sacc[i][j] - m);
                sP[row * SPS + tx * 4 + j] = p;
                rs += p;
            }
            sRed[row * 16 + tx] = rs;
        }
        __syncthreads();
        if (tid < 64) {
            float rs = 0.f;
#pragma unroll
            for (int c = 0; c < 16; c++) rs += sRed[tid * 16 + c];
            sL[tid] = sL[tid] * sF[tid] + rs;
        }
        __syncthreads();

        // rescale O and accumulate P@V
#pragma unroll
        for (int i = 0; i < 4; i++) {
            float f = sF[ty * 4 + i];
#pragma unroll
            for (int j = 0; j < 8; j++) oacc[i][j] *= f;
        }
#pragma unroll 2
        for (int kj = 0; kj < 64; kj++) {
            float p[4];
#pragma unroll
            for (int i = 0; i < 4; i++) p[i] = sP[(ty * 4 + i) * SPS + kj];
            float4 v0 = *(const float4*)&sV[kj * VSD + tx * 8];
            float4 v1 = *(const float4*)&sV[kj * VSD + tx * 8 + 4];
#pragma unroll
            for (int i = 0; i < 4; i++) {
                oacc[i][0] += p[i] * v0.x;
                oacc[i][1] += p[i] * v0.y;
                oacc[i][2] += p[i] * v0.z;
                oacc[i][3] += p[i] * v0.w;
                oacc[i][4] += p[i] * v1.x;
                oacc[i][5] += p[i] * v1.y;
                oacc[i][6] += p[i] * v1.z;
                oacc[i][7] += p[i] * v1.w;
            }
        }
    }

#pragma unroll
    for (int i = 0; i < 4; i++) {
        int row = ty * 4 + i;
        int t = qb * 64 + row;
        float inv = 1.f / sL[row];
        float4 r0 = make_float4(oacc[i][0] * inv, oacc[i][1] * inv, oacc[i][2] * inv, oacc[i][3] * inv);
        float4 r1 = make_float4(oacc[i][4] * inv, oacc[i][5] * inv, oacc[i][6] * inv, oacc[i][7] * inv);
        float* cp = ctx + (size_t)t * HH + h * HD + tx * 8;
        *(float4*)cp = r0;
        *(float4*)(cp + 4) = r1;
    }
}

// ---------------------------------------------------------------------------
// Router: one warp per token, 16 logits, softmax, top-2, renormalize
// ---------------------------------------------------------------------------
__global__ void router_kernel(const float* __restrict__ h2, const float* __restrict__ gw,
                              int* __restrict__ topi, float* __restrict__ topw) {
    int w = threadIdx.x >> 5, lane = threadIdx.x & 31;
    int t = blockIdx.x * 8 + w;
    const float* hr = h2 + (size_t)t * HH;
    float logits[NE];
#pragma unroll
    for (int e = 0; e < NE; e++) {
        float s = 0.f;
        for (int i = lane; i < HH; i += 32) s += hr[i] * gw[i * NE + e];
#pragma unroll
        for (int d = 16; d; d >>= 1) s += __shfl_xor_sync(0xffffffffu, s, d);
        logits[e] = s;
    }
    if (lane == 0) {
        float mx = -1e30f;
#pragma unroll
        for (int e = 0; e < NE; e++) mx = fmaxf(mx, logits[e]);
        float pe[NE], sum = 0.f;
#pragma unroll
        for (int e = 0; e < NE; e++) { pe[e] = expf(logits[e] - mx); sum += pe[e]; }
        float isum = 1.f / sum;
#pragma unroll
        for (int e = 0; e < NE; e++) pe[e] *= isum;
        int i1 = 0; float p1 = pe[0];
#pragma unroll
        for (int e = 1; e < NE; e++) if (pe[e] > p1) { p1 = pe[e]; i1 = e; }
        int i2 = -1; float p2 = -1.f;
#pragma unroll
        for (int e = 0; e < NE; e++) if (e != i1 && pe[e] > p2) { p2 = pe[e]; i2 = e; }
        float z = 1.f / (p1 + p2);
        topi[2 * t] = i1; topi[2 * t + 1] = i2;
        topw[2 * t] = p1 * z; topw[2 * t + 1] = p2 * z;
    }
}

// ---------------------------------------------------------------------------
// MoE routing bookkeeping
// ---------------------------------------------------------------------------
__global__ void zero_kernel(int* cnt) {
    if (threadIdx.x < NE) cnt[threadIdx.x] = 0;
}
__global__ void count_kernel(const int* __restrict__ topi, int* __restrict__ cnt) {
    int t = blockIdx.x * 256 + threadIdx.x;
    if (t < TT) {
        atomicAdd(&cnt[topi[2 * t]], 1);
        atomicAdd(&cnt[topi[2 * t + 1]], 1);
    }
}
__global__ void scan_kernel(const int* __restrict__ cnt, int* __restrict__ off,
                            int* __restrict__ cur) {
    if (threadIdx.x == 0) {
        int a = 0;
        for (int e = 0; e < NE; e++) { off[e] = a; a += cnt[e]; cur[e] = 0; }
    }
}
__global__ void scatter_kernel(const int* __restrict__ topi, const int* __restrict__ off,
                               int* __restrict__ cur, int* __restrict__ stok,
                               int* __restrict__ sof) {
    int t = blockIdx.x * 256 + threadIdx.x;
    if (t < TT) {
#pragma unroll
        for (int k = 0; k < TOPK; k++) {
            int e = topi[2 * t + k];
            int p = atomicAdd(&cur[e], 1);
            int s = off[e] + p;
            stok[s] = t;
            sof[2 * t + k] = s;
        }
    }
}

// ---------------------------------------------------------------------------
// SiLU(g) * u  (split a [rows, 2*Fdim]-strided buffer)
// ---------------------------------------------------------------------------
__global__ void silu_mul_kernel(const float* __restrict__ in, float* __restrict__ out,
                                int Fdim, int stride, int total) {
    int idx = blockIdx.x * 256 + threadIdx.x;
    if (idx < total) {
        int r = idx / Fdim, f = idx - r * Fdim;
        float gv = in[(size_t)r * stride + f];
        float uv = in[(size_t)r * stride + Fdim + f];
        out[idx] = gv / (1.f + expf(-gv)) * uv;
    }
}

// ---------------------------------------------------------------------------
// MoE combine: out[t] += w0*eout[s0] + w1*eout[s1]   (deterministic order)
// ---------------------------------------------------------------------------
__global__ void combine_kernel(const float* __restrict__ eout, const int* __restrict__ sof,
                               const float* __restrict__ topw, float* __restrict__ out) {
    int t = blockIdx.x;
    int s0 = sof[2 * t], s1 = sof[2 * t + 1];
    float w0 = topw[2 * t], w1 = topw[2 * t + 1];
    const float4* e0 = (const float4*)(eout + (size_t)s0 * HH);
    const float4* e1 = (const float4*)(eout + (size_t)s1 * HH);
    float4* orow = (float4*)(out + (size_t)t * HH);
#pragma unroll
    for (int it = 0; it < 2; it++) {
        int i = threadIdx.x + it * 256;
        float4 a = orow[i], b = e0[i], c = e1[i];
        a.x += w0 * b.x + w1 * c.x;
        a.y += w0 * b.y + w1 * c.y;
        a.z += w0 * b.z + w1 * c.z;
        a.w += w0 * b.w + w1 * c.w;
        orow[i] = a;
    }
}

// ---------------------------------------------------------------------------
// Launch
// ---------------------------------------------------------------------------
extern "C" void kernel_launch(void* const* d_in, const int* in_sizes, int n_in,
                              void* d_out, int out_size) {
    const float* x       = (const float*)d_in[0];
    const float* gamma1  = (const float*)d_in[1];
    const float* gamma2  = (const float*)d_in[2];
    const float* w_qkv   = (const float*)d_in[3];
    const float* w_o     = (const float*)d_in[4];
    const float* gate_w  = (const float*)d_in[5];
    const float* moe_up  = (const float*)d_in[6];
    const float* moe_dn  = (const float*)d_in[7];
    const float* w13     = (const float*)d_in[8];
    const float* wdn     = (const float*)d_in[9];
    float* out = (float*)d_out;

    float *h1, *qkvp, *ctx, *x1, *h2, *gu, *act, *sg, *sact, *topw;
    int *topi, *cnt, *off, *cur, *stok, *sof;
    cudaGetSymbolAddress((void**)&h1, g_h1);
    cudaGetSymbolAddress((void**)&qkvp, g_qkv);
    cudaGetSymbolAddress((void**)&ctx, g_ctx);
    cudaGetSymbolAddress((void**)&x1, g_x1);
    cudaGetSymbolAddress((void**)&h2, g_h2);
    cudaGetSymbolAddress((void**)&gu, g_gu);
    cudaGetSymbolAddress((void**)&act, g_act);
    cudaGetSymbolAddress((void**)&sg, g_sg);
    cudaGetSymbolAddress((void**)&sact, g_sact);
    cudaGetSymbolAddress((void**)&topw, g_topw);
    cudaGetSymbolAddress((void**)&topi, g_topi);
    cudaGetSymbolAddress((void**)&cnt, g_cnt);
    cudaGetSymbolAddress((void**)&off, g_off);
    cudaGetSymbolAddress((void**)&cur, g_cur);
    cudaGetSymbolAddress((void**)&stok, g_stok);
    cudaGetSymbolAddress((void**)&sof, g_sof);

    // 1. h1 = rmsnorm(x, gamma1)
    rmsnorm_kernel<<<TT, 256>>>(x, gamma1, h1);
    // 2. qkv = h1 @ w_qkv
    sgemm_k<0><<<dim3(6144 / 128, TT / 128, 1), 512>>>(h1, w_qkv, qkvp, nullptr, TT, 6144, HH,
                                                       nullptr, nullptr, nullptr);
    // 3. RoPE in place
    rope_kernel<<<TT, 256>>>(qkvp);
    // 4. attention
    cudaFuncSetAttribute(attn_kernel, cudaFuncAttributeMaxDynamicSharedMemorySize,
                         ATTN_SMEM_FLOATS * 4);
    attn_kernel<<<dim3(TT / 64, NHD), 256, ATTN_SMEM_FLOATS * 4>>>(qkvp, ctx);
    // 5. x1 = ctx @ w_o + x
    sgemm_k<1><<<dim3(HH / 128, TT / 128, 1), 512>>>(ctx, w_o, x1, x, TT, HH, HH,
                                                     nullptr, nullptr, nullptr);
    // 6. h2 = rmsnorm(x1, gamma2)
    rmsnorm_kernel<<<TT, 256>>>(x1, gamma2, h2);
    // 7. routing
    router_kernel<<<TT / 8, 256>>>(h2, gate_w, topi, topw);
    zero_kernel<<<1, 32>>>(cnt);
    count_kernel<<<TT / 256, 256>>>(topi, cnt);
    scan_kernel<<<1, 32>>>(cnt, off, cur);
    scatter_kernel<<<TT / 256, 256>>>(topi, off, cur, stok, sof);
    // 8. MoE up (gather): gu[slot] = h2[token] @ moe_up[e]
    sgemm_k<2><<<dim3(2 * FF / 128, TT / 128, NE), 512>>>(h2, moe_up, gu, nullptr, TT, 2 * FF, HH,
                                                          stok, off, cnt);
    // 9. act = silu(g) * u
    silu_mul_kernel<<<(TT * TOPK * FF) / 256, 256>>>(gu, act, FF, 2 * FF, TT * TOPK * FF);
    // 10. shared expert up
    sgemm_k<0><<<dim3(2 * FSH / 128, TT / 128, 1), 512>>>(h2, w13, sg, nullptr, TT, 2 * FSH, HH,
                                                          nullptr, nullptr, nullptr);
    silu_mul_kernel<<<(TT * FSH) / 256, 256>>>(sg, sact, FSH, 2 * FSH, TT * FSH);
    // 11. out = sact @ shared_down + x1
    sgemm_k<1><<<dim3(HH / 128, TT / 128, 1), 512>>>(sact, wdn, out, x1, TT, HH, FSH,
                                                     nullptr, nullptr, nullptr);
    // 12. MoE down: eout[slot] = act[slot] @ moe_down[e]   (reuse gu buffer as eout)
    sgemm_k<3><<<dim3(HH / 128, TT / 128, NE), 512>>>(act, moe_dn, gu, nullptr, TT, HH, FF,
                                                      stok, off, cnt);
    // 13. out[t] += w0*eout[s0] + w1*eout[s1]
    combine_kernel<<<TT, 256>>>(gu, sof, topw, out);
}